// round 3
// baseline (speedup 1.0000x reference)
#include <cuda_runtime.h>
#include <math.h>

// Problem constants
#define NB 4
#define NS 2048
#define ND 1024
#define NH 16
#define NDK 64
#define NBS (NB*NS)   // 8192

// Scratch (device globals — allocation-free per harness rules)
__device__ float g_Q[NB*NH*NS*NDK];   // [b,h,s,dk]
__device__ float g_K[NB*NH*NS*NDK];
__device__ float g_V[NB*NH*NS*NDK];
__device__ float g_O[NBS*ND];         // [b,s,d] attention output

// ---------------------------------------------------------------------------
// TN SGEMM: Out[m,n] = sum_k A[m,k]*W[n,k] + bias[n]
// A: [M=8192, K=1024] row-major, W: [N=1024, K=1024] row-major.
// BM=BN=128, BK=16, 256 threads, 8x8 micro-tile (split 64+64), double buffer.
// HEAD=true: scatter output into [b,h,s,dk] head layout.
// ---------------------------------------------------------------------------
template <bool HEAD>
__device__ __forceinline__ void gemm_body(const float* __restrict__ A,
                                          const float* __restrict__ W,
                                          const float* __restrict__ bias,
                                          float* __restrict__ Out)
{
    __shared__ float As[2][16][132];
    __shared__ float Bs[2][16][132];

    const int tid = threadIdx.x;
    const int tx  = tid & 15;
    const int ty  = tid >> 4;
    const int m0  = blockIdx.y * 128;
    const int n0  = blockIdx.x * 128;
    const int K   = ND;

    const int lr = tid >> 2;          // 0..63 : tile row
    const int lq = (tid & 3) << 2;    // 0,4,8,12 : k offset

    const float* Ap = A + (size_t)(m0 + lr) * K + lq;
    const float* Wp = W + (size_t)(n0 + lr) * K + lq;

    float acc[8][8];
#pragma unroll
    for (int i = 0; i < 8; ++i)
#pragma unroll
        for (int j = 0; j < 8; ++j) acc[i][j] = 0.f;

#define LOAD_TILE(kt, bsel) do {                                              \
        float4 a0 = *(const float4*)(Ap + (size_t)(kt)*16);                   \
        float4 a1 = *(const float4*)(Ap + (size_t)64*K + (size_t)(kt)*16);    \
        float4 b0 = *(const float4*)(Wp + (size_t)(kt)*16);                   \
        float4 b1 = *(const float4*)(Wp + (size_t)64*K + (size_t)(kt)*16);    \
        As[bsel][lq+0][lr]    = a0.x; As[bsel][lq+1][lr]    = a0.y;           \
        As[bsel][lq+2][lr]    = a0.z; As[bsel][lq+3][lr]    = a0.w;           \
        As[bsel][lq+0][lr+64] = a1.x; As[bsel][lq+1][lr+64] = a1.y;           \
        As[bsel][lq+2][lr+64] = a1.z; As[bsel][lq+3][lr+64] = a1.w;           \
        Bs[bsel][lq+0][lr]    = b0.x; Bs[bsel][lq+1][lr]    = b0.y;           \
        Bs[bsel][lq+2][lr]    = b0.z; Bs[bsel][lq+3][lr]    = b0.w;           \
        Bs[bsel][lq+0][lr+64] = b1.x; Bs[bsel][lq+1][lr+64] = b1.y;           \
        Bs[bsel][lq+2][lr+64] = b1.z; Bs[bsel][lq+3][lr+64] = b1.w;           \
    } while (0)

    LOAD_TILE(0, 0);
    __syncthreads();

    const int NK = K / 16;
    for (int kt = 0; kt < NK; ++kt) {
        const int cur = kt & 1;
        if (kt + 1 < NK) { LOAD_TILE(kt + 1, cur ^ 1); }
#pragma unroll
        for (int kk = 0; kk < 16; ++kk) {
            float a[8], b[8];
            *(float4*)&a[0] = *(const float4*)&As[cur][kk][ty * 4];
            *(float4*)&a[4] = *(const float4*)&As[cur][kk][64 + ty * 4];
            *(float4*)&b[0] = *(const float4*)&Bs[cur][kk][tx * 4];
            *(float4*)&b[4] = *(const float4*)&Bs[cur][kk][64 + tx * 4];
#pragma unroll
            for (int i = 0; i < 8; ++i)
#pragma unroll
                for (int j = 0; j < 8; ++j)
                    acc[i][j] = fmaf(a[i], b[j], acc[i][j]);
        }
        __syncthreads();
    }
#undef LOAD_TILE

    float bb[8];
    *(float4*)&bb[0] = *(const float4*)(bias + n0 + tx * 4);
    *(float4*)&bb[4] = *(const float4*)(bias + n0 + 64 + tx * 4);

#pragma unroll
    for (int i = 0; i < 8; ++i) {
        const int r = m0 + ((i < 4) ? (ty * 4 + i) : (64 + ty * 4 + (i - 4)));
#pragma unroll
        for (int g = 0; g < 2; ++g) {
            const int c0 = n0 + g * 64 + tx * 4;
            float4 o;
            o.x = acc[i][g*4+0] + bb[g*4+0];
            o.y = acc[i][g*4+1] + bb[g*4+1];
            o.z = acc[i][g*4+2] + bb[g*4+2];
            o.w = acc[i][g*4+3] + bb[g*4+3];
            size_t idx;
            if (HEAD) {
                const int bidx = r >> 11;        // r / 2048
                const int s    = r & 2047;
                const int h    = c0 >> 6;        // c0 / 64
                const int dk   = c0 & 63;
                idx = ((size_t)((bidx * NH + h) * NS + s)) * NDK + dk;
            } else {
                idx = (size_t)r * ND + c0;
            }
            *(float4*)(Out + idx) = o;
        }
    }
}

__global__ __launch_bounds__(256)
void qkv_kernel(const float* __restrict__ q,  const float* __restrict__ k,
                const float* __restrict__ v,
                const float* __restrict__ wq, const float* __restrict__ wk,
                const float* __restrict__ wv,
                const float* __restrict__ bq, const float* __restrict__ bk,
                const float* __restrict__ bv)
{
    const int z = blockIdx.z;
    const float* A  = (z == 0) ? q  : (z == 1) ? k  : v;
    const float* W  = (z == 0) ? wq : (z == 1) ? wk : wv;
    const float* bi = (z == 0) ? bq : (z == 1) ? bk : bv;
    float*       O  = (z == 0) ? g_Q : (z == 1) ? g_K : g_V;
    gemm_body<true>(A, W, bi, O);
}

__global__ __launch_bounds__(256)
void oproj_kernel(const float* __restrict__ wo, const float* __restrict__ bo,
                  float* __restrict__ out)
{
    gemm_body<false>(g_O, wo, bo, out);
}

// ---------------------------------------------------------------------------
// Flash attention: block = (qt, h, b), 64 q-rows x full S keys, 64-key tiles.
// Online softmax, exact -1e9 masking semantics (matches reference `where`).
// smem: Qs[d][r] (d-major), KPs = K d-major then P [k][r], Vs[k][d]. Pad 68.
// Each 64x64 tile = 1024 float4 = 4 float4 per thread (columns c+lq,
// c in {0,16,32,48}) — full coverage.
// ---------------------------------------------------------------------------
__global__ __launch_bounds__(256)
void attn_kernel(const int* __restrict__ mask)
{
    extern __shared__ float sm[];
    float* Qs  = sm;               // [64][68]
    float* KPs = sm + 64 * 68;     // [64][68]
    float* Vs  = sm + 2 * 64 * 68; // [64][68]

    const int tid = threadIdx.x;
    const int tx  = tid & 15;
    const int ty  = tid >> 4;
    const int qt  = blockIdx.x;
    const int h   = blockIdx.y;
    const int b   = blockIdx.z;

    const float* Qbase = g_Q + ((size_t)(b * NH + h) * NS + qt * 64) * NDK;
    const float* Kbase = g_K + (size_t)(b * NH + h) * NS * NDK;
    const float* Vbase = g_V + (size_t)(b * NH + h) * NS * NDK;
    const int*   mrow  = mask + b * NS;

    const int lr = tid >> 2;          // 0..63 : tile row
    const int lq = (tid & 3) << 2;    // 0,4,8,12 : column sub-offset

    // Q tile, transposed to d-major: 4 float4 per thread covers all 64 cols
#pragma unroll
    for (int c = 0; c < 64; c += 16) {
        float4 qv = *(const float4*)(Qbase + lr * 64 + c + lq);
        Qs[(c + lq + 0) * 68 + lr] = qv.x;
        Qs[(c + lq + 1) * 68 + lr] = qv.y;
        Qs[(c + lq + 2) * 68 + lr] = qv.z;
        Qs[(c + lq + 3) * 68 + lr] = qv.w;
    }

    float m_i[4], l_i[4], acc[4][4];
#pragma unroll
    for (int i = 0; i < 4; ++i) {
        m_i[i] = -INFINITY; l_i[i] = 0.f;
#pragma unroll
        for (int j = 0; j < 4; ++j) acc[i][j] = 0.f;
    }

    for (int kt = 0; kt < NS / 64; ++kt) {
        __syncthreads();   // prior-iter P/V consumers done before overwrite
        {
            const float* Kt = Kbase + (size_t)kt * 64 * 64;
            const float* Vt = Vbase + (size_t)kt * 64 * 64;
#pragma unroll
            for (int c = 0; c < 64; c += 16) {
                float4 kv = *(const float4*)(Kt + lr * 64 + c + lq);
                KPs[(c + lq + 0) * 68 + lr] = kv.x;
                KPs[(c + lq + 1) * 68 + lr] = kv.y;
                KPs[(c + lq + 2) * 68 + lr] = kv.z;
                KPs[(c + lq + 3) * 68 + lr] = kv.w;
                float4 vv = *(const float4*)(Vt + lr * 64 + c + lq);
                *(float4*)(Vs + lr * 68 + c + lq) = vv;
            }
        }
        const int4 mk = *(const int4*)(mrow + kt * 64 + tx * 4);
        __syncthreads();

        // S = Q @ K^T
        float s[4][4];
#pragma unroll
        for (int i = 0; i < 4; ++i)
#pragma unroll
            for (int j = 0; j < 4; ++j) s[i][j] = 0.f;

#pragma unroll 16
        for (int d = 0; d < 64; ++d) {
            float qa[4], kb[4];
            *(float4*)qa = *(const float4*)&Qs[d * 68 + ty * 4];
            *(float4*)kb = *(const float4*)&KPs[d * 68 + tx * 4];
#pragma unroll
            for (int i = 0; i < 4; ++i)
#pragma unroll
                for (int j = 0; j < 4; ++j)
                    s[i][j] = fmaf(qa[i], kb[j], s[i][j]);
        }

        // scale + mask (exactly -1e9 like the reference), then online softmax
        float pm[4];
#pragma unroll
        for (int i = 0; i < 4; ++i) {
            float v0 = (mk.x == 0) ? -1e9f : s[i][0] * 0.125f;
            float v1 = (mk.y == 0) ? -1e9f : s[i][1] * 0.125f;
            float v2 = (mk.z == 0) ? -1e9f : s[i][2] * 0.125f;
            float v3 = (mk.w == 0) ? -1e9f : s[i][3] * 0.125f;
            s[i][0] = v0; s[i][1] = v1; s[i][2] = v2; s[i][3] = v3;
            pm[i] = fmaxf(fmaxf(v0, v1), fmaxf(v2, v3));
        }
#pragma unroll
        for (int o = 1; o < 16; o <<= 1)
#pragma unroll
            for (int i = 0; i < 4; ++i)
                pm[i] = fmaxf(pm[i], __shfl_xor_sync(0xffffffffu, pm[i], o));

#pragma unroll
        for (int i = 0; i < 4; ++i) {
            const float mnew  = fmaxf(m_i[i], pm[i]);
            const float alpha = __expf(m_i[i] - mnew);
            m_i[i] = mnew;
            float rs = 0.f;
#pragma unroll
            for (int j = 0; j < 4; ++j) {
                const float p = __expf(s[i][j] - mnew);
                s[i][j] = p;
                rs += p;
            }
#pragma unroll
            for (int o = 1; o < 16; o <<= 1)
                rs += __shfl_xor_sync(0xffffffffu, rs, o);
            l_i[i] = l_i[i] * alpha + rs;
#pragma unroll
            for (int j = 0; j < 4; ++j) acc[i][j] *= alpha;
        }

        __syncthreads();   // all K reads done before P overlays the buffer
#pragma unroll
        for (int j = 0; j < 4; ++j)
#pragma unroll
            for (int i = 0; i < 4; ++i)
                KPs[(tx * 4 + j) * 68 + (ty * 4 + i)] = s[i][j];
        __syncthreads();

        // O += P @ V
#pragma unroll 16
        for (int k2 = 0; k2 < 64; ++k2) {
            float pa[4], vb[4];
            *(float4*)pa = *(const float4*)&KPs[k2 * 68 + ty * 4];
            *(float4*)vb = *(const float4*)&Vs[k2 * 68 + tx * 4];
#pragma unroll
            for (int i = 0; i < 4; ++i)
#pragma unroll
                for (int j = 0; j < 4; ++j)
                    acc[i][j] = fmaf(pa[i], vb[j], acc[i][j]);
        }
    }

#pragma unroll
    for (int i = 0; i < 4; ++i) {
        const float inv  = 1.f / l_i[i];
        const int   srow = qt * 64 + ty * 4 + i;
        float4 o;
        o.x = acc[i][0] * inv; o.y = acc[i][1] * inv;
        o.z = acc[i][2] * inv; o.w = acc[i][3] * inv;
        *(float4*)(g_O + (size_t)(b * NS + srow) * ND + h * 64 + tx * 4) = o;
    }
}

// ---------------------------------------------------------------------------
// Input-order detection (kept: robust to either metadata ordering):
//   setup order: query,key,value,mask,wq,bq,wk,bk,wv,bv,wo,bo  -> in_sizes[0]==8388608
//   alphabetical: bk,bo,bq,bv,key,mask,query,value,wk,wo,wq,wv -> in_sizes[0]==1024
// ---------------------------------------------------------------------------
extern "C" void kernel_launch(void* const* d_in, const int* in_sizes, int n_in,
                              void* d_out, int out_size)
{
    (void)n_in; (void)out_size;
    const float *query, *key, *value, *wq, *bq, *wk, *bk, *wv, *bv, *wo, *bo;
    const int *mask;

    if (in_sizes[0] == NB * NS * ND) {
        // setup_inputs dict order
        query = (const float*)d_in[0];
        key   = (const float*)d_in[1];
        value = (const float*)d_in[2];
        mask  = (const int*)  d_in[3];
        wq    = (const float*)d_in[4];
        bq    = (const float*)d_in[5];
        wk    = (const float*)d_in[6];
        bk    = (const float*)d_in[7];
        wv    = (const float*)d_in[8];
        bv    = (const float*)d_in[9];
        wo    = (const float*)d_in[10];
        bo    = (const float*)d_in[11];
    } else {
        // alphabetical order: bk,bo,bq,bv,key,mask,query,value,wk,wo,wq,wv
        bk    = (const float*)d_in[0];
        bo    = (const float*)d_in[1];
        bq    = (const float*)d_in[2];
        bv    = (const float*)d_in[3];
        key   = (const float*)d_in[4];
        mask  = (const int*)  d_in[5];
        query = (const float*)d_in[6];
        value = (const float*)d_in[7];
        wk    = (const float*)d_in[8];
        wo    = (const float*)d_in[9];
        wq    = (const float*)d_in[10];
        wv    = (const float*)d_in[11];
    }

    // 1) QKV projections (z = 0/1/2)
    dim3 gProj(ND / 128, NBS / 128, 3);
    qkv_kernel<<<gProj, 256>>>(query, key, value, wq, wk, wv, bq, bk, bv);

    // 2) flash attention (52224 B dynamic smem > 48KB default -> raise cap)
    const int smemBytes = 3 * 64 * 68 * (int)sizeof(float);
    cudaFuncSetAttribute(attn_kernel,
                         cudaFuncAttributeMaxDynamicSharedMemorySize, smemBytes);
    attn_kernel<<<dim3(NS / 64, NH, NB), 256, smemBytes>>>(mask);

    // 3) output projection
    oproj_kernel<<<dim3(ND / 128, NBS / 128, 1), 256>>>(wo, bo, (float*)d_out);
}

// round 5
// speedup vs baseline: 1.2682x; 1.2682x over previous
#include <cuda_runtime.h>
#include <cuda_bf16.h>
#include <math.h>
#include <stdint.h>

// Problem constants
#define NB 4
#define NS 2048
#define ND 1024
#define NH 16
#define NDK 64
#define NBS (NB*NS)   // 8192

// Scratch (device globals — allocation-free per harness rules)
__device__ float g_Q[NB*NH*NS*NDK];   // [b,h,s,dk]
__device__ float g_K[NB*NH*NS*NDK];
__device__ float g_V[NB*NH*NS*NDK];
__device__ float g_O[NBS*ND];         // [b,s,d] attention output

// ===========================================================================
// Base-ISA tensor core helpers (mma.sync + ldmatrix; no 'a'-gated features)
// ===========================================================================
__device__ __forceinline__ uint32_t smem_u32(const void* p) {
    uint32_t a;
    asm("{ .reg .u64 t; cvta.to.shared.u64 t, %1; cvt.u32.u64 %0, t; }"
        : "=r"(a) : "l"(p));
    return a;
}

__device__ __forceinline__ void ldsm4(uint32_t addr, uint32_t& r0, uint32_t& r1,
                                      uint32_t& r2, uint32_t& r3) {
    asm volatile("ldmatrix.sync.aligned.m8n8.x4.shared.b16 {%0,%1,%2,%3}, [%4];"
                 : "=r"(r0), "=r"(r1), "=r"(r2), "=r"(r3) : "r"(addr));
}

__device__ __forceinline__ void mma16816(float* c, const uint32_t* a,
                                         uint32_t b0, uint32_t b1) {
    asm volatile(
        "mma.sync.aligned.m16n8k16.row.col.f32.bf16.bf16.f32 "
        "{%0,%1,%2,%3}, {%4,%5,%6,%7}, {%8,%9}, {%0,%1,%2,%3};"
        : "+f"(c[0]), "+f"(c[1]), "+f"(c[2]), "+f"(c[3])
        : "r"(a[0]), "r"(a[1]), "r"(a[2]), "r"(a[3]), "r"(b0), "r"(b1));
}

__device__ __forceinline__ uint32_t pack_bf2(__nv_bfloat16 lo, __nv_bfloat16 hi) {
    return ((uint32_t)__bfloat16_as_ushort(hi) << 16) | __bfloat16_as_ushort(lo);
}

// fp32x4 -> bf16 hi (uint2) + bf16 lo-residual (uint2)
__device__ __forceinline__ void split4(float4 v, uint2& h, uint2& l) {
    __nv_bfloat16 h0 = __float2bfloat16_rn(v.x);
    __nv_bfloat16 h1 = __float2bfloat16_rn(v.y);
    __nv_bfloat16 h2 = __float2bfloat16_rn(v.z);
    __nv_bfloat16 h3 = __float2bfloat16_rn(v.w);
    h.x = pack_bf2(h0, h1);
    h.y = pack_bf2(h2, h3);
    l.x = pack_bf2(__float2bfloat16_rn(v.x - __bfloat162float(h0)),
                   __float2bfloat16_rn(v.y - __bfloat162float(h1)));
    l.y = pack_bf2(__float2bfloat16_rn(v.z - __bfloat162float(h2)),
                   __float2bfloat16_rn(v.w - __bfloat162float(h3)));
}

// SMEM per stage: 4 tiles (A_hi, A_lo, B_hi, B_lo), each 128 rows x 40 bf16
// (32 data + 8 pad) = 10240 B. Stage = 40960 B; 2 stages = 81920 B.
#define TILE_B   10240
#define STAGE_B  40960
#define GEMM_SMEM (2*STAGE_B)

// ===========================================================================
// Split-bf16 3-term TN GEMM on mma.sync:
//   Out[m,n] = sum_k A[m,k]*W[n,k] + bias[n],  error ~2^-16 (Al*Bl dropped)
// Tile 128x128, K-chunks of 32, 8 warps (2x4), 64x32 per warp.
// HEAD=true: scatter output into [b,h,s,dk] head layout.
// ===========================================================================
template <bool HEAD>
__device__ void gemm_mma_body(const float* __restrict__ A,
                              const float* __restrict__ W,
                              const float* __restrict__ bias,
                              float* __restrict__ Out)
{
    extern __shared__ char smem[];
    const uint32_t sb = smem_u32(smem);
    const int tid  = threadIdx.x;
    const int lane = tid & 31;
    const int wid  = tid >> 5;
    const int wm   = wid >> 2;     // 0..1
    const int wn   = wid & 3;      // 0..3
    const int m0   = blockIdx.y * 128;
    const int n0   = blockIdx.x * 128;

    float acc[4][4][4];
#pragma unroll
    for (int i = 0; i < 4; ++i)
#pragma unroll
        for (int j = 0; j < 4; ++j)
#pragma unroll
            for (int r = 0; r < 4; ++r) acc[i][j][r] = 0.f;

    float4 afr[4], bfr[4];

#define LDGC(c) do {                                                          \
        _Pragma("unroll")                                                     \
        for (int i = 0; i < 4; ++i) {                                         \
            const int li = tid + 256 * i;                                     \
            const int row = li >> 3, f4 = li & 7;                             \
            afr[i] = *(const float4*)(A + (size_t)(m0 + row) * 1024 + (c) * 32 + f4 * 4); \
            bfr[i] = *(const float4*)(W + (size_t)(n0 + row) * 1024 + (c) * 32 + f4 * 4); \
        }                                                                     \
    } while (0)

#define STSC(s) do {                                                          \
        char* st = smem + (s) * STAGE_B;                                      \
        _Pragma("unroll")                                                     \
        for (int i = 0; i < 4; ++i) {                                         \
            const int li = tid + 256 * i;                                     \
            const int row = li >> 3, f4 = li & 7;                             \
            const uint32_t off = (uint32_t)(row * 80 + f4 * 8);               \
            uint2 h, l;                                                       \
            split4(afr[i], h, l);                                             \
            *(uint2*)(st + off)              = h;                             \
            *(uint2*)(st + TILE_B + off)     = l;                             \
            split4(bfr[i], h, l);                                             \
            *(uint2*)(st + 2 * TILE_B + off) = h;                             \
            *(uint2*)(st + 3 * TILE_B + off) = l;                             \
        }                                                                     \
    } while (0)

    // ldmatrix lane addressing (element offsets within a tile row of 40 bf16)
    const int ar  = lane & 15;                       // A: row within 16
    const int akz = (lane >> 4) << 3;                // A: +8 k for upper half
    const int br  = ((lane >> 4) << 3) + (lane & 7); // B: n row within 16
    const int bkz = ((lane >> 3) & 1) << 3;          // B: +8 k

#define COMP(s) do {                                                          \
        const uint32_t st = sb + (s) * STAGE_B;                               \
        const uint32_t Ah = st, Al = st + TILE_B;                             \
        const uint32_t Bh = st + 2 * TILE_B, Bl = st + 3 * TILE_B;            \
        _Pragma("unroll")                                                     \
        for (int kk = 0; kk < 2; ++kk) {                                      \
            uint32_t ahf[4][4], alf[4][4];                                    \
            _Pragma("unroll")                                                 \
            for (int i = 0; i < 4; ++i) {                                     \
                const uint32_t off =                                          \
                    (uint32_t)((wm * 64 + i * 16 + ar) * 80 + (kk * 16 + akz) * 2); \
                ldsm4(Ah + off, ahf[i][0], ahf[i][1], ahf[i][2], ahf[i][3]);  \
                ldsm4(Al + off, alf[i][0], alf[i][1], alf[i][2], alf[i][3]);  \
            }                                                                 \
            uint32_t bhf[2][4], blf[2][4];                                    \
            _Pragma("unroll")                                                 \
            for (int jj = 0; jj < 2; ++jj) {                                  \
                const uint32_t off =                                          \
                    (uint32_t)((wn * 32 + jj * 16 + br) * 80 + (kk * 16 + bkz) * 2); \
                ldsm4(Bh + off, bhf[jj][0], bhf[jj][1], bhf[jj][2], bhf[jj][3]); \
                ldsm4(Bl + off, blf[jj][0], blf[jj][1], blf[jj][2], blf[jj][3]); \
            }                                                                 \
            _Pragma("unroll")                                                 \
            for (int i = 0; i < 4; ++i)                                       \
                _Pragma("unroll")                                             \
                for (int j = 0; j < 4; ++j) {                                 \
                    const uint32_t b0h = bhf[j >> 1][(j & 1) * 2];            \
                    const uint32_t b1h = bhf[j >> 1][(j & 1) * 2 + 1];        \
                    const uint32_t b0l = blf[j >> 1][(j & 1) * 2];            \
                    const uint32_t b1l = blf[j >> 1][(j & 1) * 2 + 1];        \
                    mma16816(acc[i][j], ahf[i], b0h, b1h);                    \
                    mma16816(acc[i][j], ahf[i], b0l, b1l);                    \
                    mma16816(acc[i][j], alf[i], b0h, b1h);                    \
                }                                                             \
        }                                                                     \
    } while (0)

    LDGC(0);
    STSC(0);
    __syncthreads();

    for (int c = 0; c < 32; ++c) {
        if (c < 31) LDGC(c + 1);
        COMP(c & 1);
        if (c < 31) STSC((c + 1) & 1);
        __syncthreads();
    }
#undef LDGC
#undef STSC
#undef COMP

    // Epilogue: C frags -> bias add -> (head-)scatter, float2 stores
    const int g  = lane >> 2;
    const int qd = lane & 3;
#pragma unroll
    for (int i = 0; i < 4; ++i) {
        const int mA = m0 + wm * 64 + i * 16 + g;
        const int mB = mA + 8;
#pragma unroll
        for (int j = 0; j < 4; ++j) {
            const int n = n0 + wn * 32 + j * 8 + qd * 2;
            const float2 bv = *(const float2*)(bias + n);
            float2 o1, o2;
            o1.x = acc[i][j][0] + bv.x;  o1.y = acc[i][j][1] + bv.y;
            o2.x = acc[i][j][2] + bv.x;  o2.y = acc[i][j][3] + bv.y;
            if (HEAD) {
                const int h = n >> 6, dk = n & 63;
                const int b1 = mA >> 11, s1 = mA & 2047;
                const int b2 = mB >> 11, s2 = mB & 2047;
                *(float2*)(Out + ((size_t)((b1 * NH + h) * NS + s1)) * NDK + dk) = o1;
                *(float2*)(Out + ((size_t)((b2 * NH + h) * NS + s2)) * NDK + dk) = o2;
            } else {
                *(float2*)(Out + (size_t)mA * ND + n) = o1;
                *(float2*)(Out + (size_t)mB * ND + n) = o2;
            }
        }
    }
}

__global__ __launch_bounds__(256)
void qkv_mma(const float* __restrict__ q,  const float* __restrict__ k,
             const float* __restrict__ v,
             const float* __restrict__ wq, const float* __restrict__ wk,
             const float* __restrict__ wv,
             const float* __restrict__ bq, const float* __restrict__ bk,
             const float* __restrict__ bv)
{
    const int z = blockIdx.z;
    const float* A  = (z == 0) ? q  : (z == 1) ? k  : v;
    const float* W  = (z == 0) ? wq : (z == 1) ? wk : wv;
    const float* bi = (z == 0) ? bq : (z == 1) ? bk : bv;
    float*       O  = (z == 0) ? g_Q : (z == 1) ? g_K : g_V;
    gemm_mma_body<true>(A, W, bi, O);
}

__global__ __launch_bounds__(256)
void oproj_mma(const float* __restrict__ wo, const float* __restrict__ bo,
               float* __restrict__ out)
{
    gemm_mma_body<false>(g_O, wo, bo, out);
}

// ---------------------------------------------------------------------------
// Flash attention (fp32 FFMA — unchanged from the passing round 3 kernel)
// ---------------------------------------------------------------------------
__global__ __launch_bounds__(256)
void attn_kernel(const int* __restrict__ mask)
{
    extern __shared__ float sm[];
    float* Qs  = sm;               // [64][68]
    float* KPs = sm + 64 * 68;     // [64][68]
    float* Vs  = sm + 2 * 64 * 68; // [64][68]

    const int tid = threadIdx.x;
    const int tx  = tid & 15;
    const int ty  = tid >> 4;
    const int qt  = blockIdx.x;
    const int h   = blockIdx.y;
    const int b   = blockIdx.z;

    const float* Qbase = g_Q + ((size_t)(b * NH + h) * NS + qt * 64) * NDK;
    const float* Kbase = g_K + (size_t)(b * NH + h) * NS * NDK;
    const float* Vbase = g_V + (size_t)(b * NH + h) * NS * NDK;
    const int*   mrow  = mask + b * NS;

    const int lr = tid >> 2;
    const int lq = (tid & 3) << 2;

#pragma unroll
    for (int c = 0; c < 64; c += 16) {
        float4 qv = *(const float4*)(Qbase + lr * 64 + c + lq);
        Qs[(c + lq + 0) * 68 + lr] = qv.x;
        Qs[(c + lq + 1) * 68 + lr] = qv.y;
        Qs[(c + lq + 2) * 68 + lr] = qv.z;
        Qs[(c + lq + 3) * 68 + lr] = qv.w;
    }

    float m_i[4], l_i[4], acc[4][4];
#pragma unroll
    for (int i = 0; i < 4; ++i) {
        m_i[i] = -INFINITY; l_i[i] = 0.f;
#pragma unroll
        for (int j = 0; j < 4; ++j) acc[i][j] = 0.f;
    }

    for (int kt = 0; kt < NS / 64; ++kt) {
        __syncthreads();
        {
            const float* Kt = Kbase + (size_t)kt * 64 * 64;
            const float* Vt = Vbase + (size_t)kt * 64 * 64;
#pragma unroll
            for (int c = 0; c < 64; c += 16) {
                float4 kv = *(const float4*)(Kt + lr * 64 + c + lq);
                KPs[(c + lq + 0) * 68 + lr] = kv.x;
                KPs[(c + lq + 1) * 68 + lr] = kv.y;
                KPs[(c + lq + 2) * 68 + lr] = kv.z;
                KPs[(c + lq + 3) * 68 + lr] = kv.w;
                float4 vv = *(const float4*)(Vt + lr * 64 + c + lq);
                *(float4*)(Vs + lr * 68 + c + lq) = vv;
            }
        }
        const int4 mk = *(const int4*)(mrow + kt * 64 + tx * 4);
        __syncthreads();

        float s[4][4];
#pragma unroll
        for (int i = 0; i < 4; ++i)
#pragma unroll
            for (int j = 0; j < 4; ++j) s[i][j] = 0.f;

#pragma unroll 16
        for (int d = 0; d < 64; ++d) {
            float qa[4], kb[4];
            *(float4*)qa = *(const float4*)&Qs[d * 68 + ty * 4];
            *(float4*)kb = *(const float4*)&KPs[d * 68 + tx * 4];
#pragma unroll
            for (int i = 0; i < 4; ++i)
#pragma unroll
                for (int j = 0; j < 4; ++j)
                    s[i][j] = fmaf(qa[i], kb[j], s[i][j]);
        }

        float pm[4];
#pragma unroll
        for (int i = 0; i < 4; ++i) {
            float v0 = (mk.x == 0) ? -1e9f : s[i][0] * 0.125f;
            float v1 = (mk.y == 0) ? -1e9f : s[i][1] * 0.125f;
            float v2 = (mk.z == 0) ? -1e9f : s[i][2] * 0.125f;
            float v3 = (mk.w == 0) ? -1e9f : s[i][3] * 0.125f;
            s[i][0] = v0; s[i][1] = v1; s[i][2] = v2; s[i][3] = v3;
            pm[i] = fmaxf(fmaxf(v0, v1), fmaxf(v2, v3));
        }
#pragma unroll
        for (int o = 1; o < 16; o <<= 1)
#pragma unroll
            for (int i = 0; i < 4; ++i)
                pm[i] = fmaxf(pm[i], __shfl_xor_sync(0xffffffffu, pm[i], o));

#pragma unroll
        for (int i = 0; i < 4; ++i) {
            const float mnew  = fmaxf(m_i[i], pm[i]);
            const float alpha = __expf(m_i[i] - mnew);
            m_i[i] = mnew;
            float rs = 0.f;
#pragma unroll
            for (int j = 0; j < 4; ++j) {
                const float p = __expf(s[i][j] - mnew);
                s[i][j] = p;
                rs += p;
            }
#pragma unroll
            for (int o = 1; o < 16; o <<= 1)
                rs += __shfl_xor_sync(0xffffffffu, rs, o);
            l_i[i] = l_i[i] * alpha + rs;
#pragma unroll
            for (int j = 0; j < 4; ++j) acc[i][j] *= alpha;
        }

        __syncthreads();
#pragma unroll
        for (int j = 0; j < 4; ++j)
#pragma unroll
            for (int i = 0; i < 4; ++i)
                KPs[(tx * 4 + j) * 68 + (ty * 4 + i)] = s[i][j];
        __syncthreads();

#pragma unroll 16
        for (int k2 = 0; k2 < 64; ++k2) {
            float pa[4], vb[4];
            *(float4*)pa = *(const float4*)&KPs[k2 * 68 + ty * 4];
            *(float4*)vb = *(const float4*)&Vs[k2 * 68 + tx * 4];
#pragma unroll
            for (int i = 0; i < 4; ++i)
#pragma unroll
                for (int j = 0; j < 4; ++j)
                    acc[i][j] = fmaf(pa[i], vb[j], acc[i][j]);
        }
    }

#pragma unroll
    for (int i = 0; i < 4; ++i) {
        const float inv  = 1.f / l_i[i];
        const int   srow = qt * 64 + ty * 4 + i;
        float4 o;
        o.x = acc[i][0] * inv; o.y = acc[i][1] * inv;
        o.z = acc[i][2] * inv; o.w = acc[i][3] * inv;
        *(float4*)(g_O + (size_t)(b * NS + srow) * ND + h * 64 + tx * 4) = o;
    }
}

// ---------------------------------------------------------------------------
extern "C" void kernel_launch(void* const* d_in, const int* in_sizes, int n_in,
                              void* d_out, int out_size)
{
    (void)n_in; (void)out_size;
    const float *query, *key, *value, *wq, *bq, *wk, *bk, *wv, *bv, *wo, *bo;
    const int *mask;

    if (in_sizes[0] == NB * NS * ND) {
        query = (const float*)d_in[0];
        key   = (const float*)d_in[1];
        value = (const float*)d_in[2];
        mask  = (const int*)  d_in[3];
        wq    = (const float*)d_in[4];
        bq    = (const float*)d_in[5];
        wk    = (const float*)d_in[6];
        bk    = (const float*)d_in[7];
        wv    = (const float*)d_in[8];
        bv    = (const float*)d_in[9];
        wo    = (const float*)d_in[10];
        bo    = (const float*)d_in[11];
    } else {
        bk    = (const float*)d_in[0];
        bo    = (const float*)d_in[1];
        bq    = (const float*)d_in[2];
        bv    = (const float*)d_in[3];
        key   = (const float*)d_in[4];
        mask  = (const int*)  d_in[5];
        query = (const float*)d_in[6];
        value = (const float*)d_in[7];
        wk    = (const float*)d_in[8];
        wo    = (const float*)d_in[9];
        wq    = (const float*)d_in[10];
        wv    = (const float*)d_in[11];
    }

    cudaFuncSetAttribute(qkv_mma,   cudaFuncAttributeMaxDynamicSharedMemorySize, GEMM_SMEM);
    cudaFuncSetAttribute(oproj_mma, cudaFuncAttributeMaxDynamicSharedMemorySize, GEMM_SMEM);
    const int attnSmem = 3 * 64 * 68 * (int)sizeof(float);
    cudaFuncSetAttribute(attn_kernel, cudaFuncAttributeMaxDynamicSharedMemorySize, attnSmem);

    // 1) QKV projections (split-bf16 mma.sync)
    qkv_mma<<<dim3(ND / 128, NBS / 128, 3), 256, GEMM_SMEM>>>(
        query, key, value, wq, wk, wv, bq, bk, bv);

    // 2) flash attention (fp32)
    attn_kernel<<<dim3(NS / 64, NH, NB), 256, attnSmem>>>(mask);

    // 3) output projection (split-bf16 mma.sync)
    oproj_mma<<<dim3(ND / 128, NBS / 128, 1), 256, GEMM_SMEM>>>(wo, bo, (float*)d_out);
}

// round 6
// speedup vs baseline: 2.3858x; 1.8813x over previous
#include <cuda_runtime.h>
#include <cuda_bf16.h>
#include <math.h>
#include <stdint.h>

// Problem constants
#define NB 4
#define NS 2048
#define ND 1024
#define NH 16
#define NDK 64
#define NBS (NB*NS)   // 8192

// Scratch (device globals — allocation-free per harness rules)
__device__ __nv_bfloat16 g_Qh[NB*NH*NS*NDK], g_Ql[NB*NH*NS*NDK];
__device__ __nv_bfloat16 g_Kh[NB*NH*NS*NDK], g_Kl[NB*NH*NS*NDK];
__device__ __nv_bfloat16 g_Vh[NB*NH*NS*NDK], g_Vl[NB*NH*NS*NDK];
__device__ float g_O[NBS*ND];         // [b,s,d] attention output (fp32)

// ===========================================================================
// Base-ISA tensor core helpers (mma.sync + ldmatrix + cp.async)
// ===========================================================================
__device__ __forceinline__ uint32_t smem_u32(const void* p) {
    uint32_t a;
    asm("{ .reg .u64 t; cvta.to.shared.u64 t, %1; cvt.u32.u64 %0, t; }"
        : "=r"(a) : "l"(p));
    return a;
}

__device__ __forceinline__ void ldsm4(uint32_t addr, uint32_t& r0, uint32_t& r1,
                                      uint32_t& r2, uint32_t& r3) {
    asm volatile("ldmatrix.sync.aligned.m8n8.x4.shared.b16 {%0,%1,%2,%3}, [%4];"
                 : "=r"(r0), "=r"(r1), "=r"(r2), "=r"(r3) : "r"(addr));
}
__device__ __forceinline__ void ldsm4t(uint32_t addr, uint32_t& r0, uint32_t& r1,
                                       uint32_t& r2, uint32_t& r3) {
    asm volatile("ldmatrix.sync.aligned.m8n8.x4.trans.shared.b16 {%0,%1,%2,%3}, [%4];"
                 : "=r"(r0), "=r"(r1), "=r"(r2), "=r"(r3) : "r"(addr));
}

__device__ __forceinline__ void mma16816(float* c, const uint32_t* a,
                                         uint32_t b0, uint32_t b1) {
    asm volatile(
        "mma.sync.aligned.m16n8k16.row.col.f32.bf16.bf16.f32 "
        "{%0,%1,%2,%3}, {%4,%5,%6,%7}, {%8,%9}, {%0,%1,%2,%3};"
        : "+f"(c[0]), "+f"(c[1]), "+f"(c[2]), "+f"(c[3])
        : "r"(a[0]), "r"(a[1]), "r"(a[2]), "r"(a[3]), "r"(b0), "r"(b1));
}

__device__ __forceinline__ void cp16(uint32_t dst, const void* src) {
    asm volatile("cp.async.cg.shared.global [%0], [%1], 16;"
                 :: "r"(dst), "l"(src) : "memory");
}
#define CP_COMMIT asm volatile("cp.async.commit_group;" ::: "memory")
#define CP_WAIT1  asm volatile("cp.async.wait_group 1;" ::: "memory")
#define CP_WAIT0  asm volatile("cp.async.wait_group 0;" ::: "memory")

__device__ __forceinline__ float ex2(float x) {
    float y;
    asm("ex2.approx.f32 %0, %1;" : "=f"(y) : "f"(x));
    return y;
}

__device__ __forceinline__ uint32_t pack_bf2(__nv_bfloat16 lo, __nv_bfloat16 hi) {
    return ((uint32_t)__bfloat16_as_ushort(hi) << 16) | __bfloat16_as_ushort(lo);
}

__device__ __forceinline__ void split4(float4 v, uint2& h, uint2& l) {
    __nv_bfloat16 h0 = __float2bfloat16_rn(v.x);
    __nv_bfloat16 h1 = __float2bfloat16_rn(v.y);
    __nv_bfloat16 h2 = __float2bfloat16_rn(v.z);
    __nv_bfloat16 h3 = __float2bfloat16_rn(v.w);
    h.x = pack_bf2(h0, h1);
    h.y = pack_bf2(h2, h3);
    l.x = pack_bf2(__float2bfloat16_rn(v.x - __bfloat162float(h0)),
                   __float2bfloat16_rn(v.y - __bfloat162float(h1)));
    l.y = pack_bf2(__float2bfloat16_rn(v.z - __bfloat162float(h2)),
                   __float2bfloat16_rn(v.w - __bfloat162float(h3)));
}
__device__ __forceinline__ void split2(float2 v, uint32_t& h, uint32_t& l) {
    __nv_bfloat16 h0 = __float2bfloat16_rn(v.x);
    __nv_bfloat16 h1 = __float2bfloat16_rn(v.y);
    h = pack_bf2(h0, h1);
    l = pack_bf2(__float2bfloat16_rn(v.x - __bfloat162float(h0)),
                 __float2bfloat16_rn(v.y - __bfloat162float(h1)));
}

// ===========================================================================
// Split-bf16 3-term TN GEMM (unchanged core from round 5; HEAD epilogue now
// writes bf16 hi/lo head-layout arrays for the attention kernel)
// ===========================================================================
#define TILE_B   10240
#define STAGE_B  40960
#define GEMM_SMEM (2*STAGE_B)

template <bool HEAD>
__device__ void gemm_mma_body(const float* __restrict__ A,
                              const float* __restrict__ W,
                              const float* __restrict__ bias,
                              float* __restrict__ Out,
                              __nv_bfloat16* __restrict__ Oh,
                              __nv_bfloat16* __restrict__ Ol)
{
    extern __shared__ char smem[];
    const uint32_t sb = smem_u32(smem);
    const int tid  = threadIdx.x;
    const int lane = tid & 31;
    const int wid  = tid >> 5;
    const int wm   = wid >> 2;
    const int wn   = wid & 3;
    const int m0   = blockIdx.y * 128;
    const int n0   = blockIdx.x * 128;

    float acc[4][4][4];
#pragma unroll
    for (int i = 0; i < 4; ++i)
#pragma unroll
        for (int j = 0; j < 4; ++j)
#pragma unroll
            for (int r = 0; r < 4; ++r) acc[i][j][r] = 0.f;

    float4 afr[4], bfr[4];

#define LDGC(c) do {                                                          \
        _Pragma("unroll")                                                     \
        for (int i = 0; i < 4; ++i) {                                         \
            const int li = tid + 256 * i;                                     \
            const int row = li >> 3, f4 = li & 7;                             \
            afr[i] = *(const float4*)(A + (size_t)(m0 + row) * 1024 + (c) * 32 + f4 * 4); \
            bfr[i] = *(const float4*)(W + (size_t)(n0 + row) * 1024 + (c) * 32 + f4 * 4); \
        }                                                                     \
    } while (0)

#define STSC(s) do {                                                          \
        char* st = smem + (s) * STAGE_B;                                      \
        _Pragma("unroll")                                                     \
        for (int i = 0; i < 4; ++i) {                                         \
            const int li = tid + 256 * i;                                     \
            const int row = li >> 3, f4 = li & 7;                             \
            const uint32_t off = (uint32_t)(row * 80 + f4 * 8);               \
            uint2 h, l;                                                       \
            split4(afr[i], h, l);                                             \
            *(uint2*)(st + off)              = h;                             \
            *(uint2*)(st + TILE_B + off)     = l;                             \
            split4(bfr[i], h, l);                                             \
            *(uint2*)(st + 2 * TILE_B + off) = h;                             \
            *(uint2*)(st + 3 * TILE_B + off) = l;                             \
        }                                                                     \
    } while (0)

    const int ar  = lane & 15;
    const int akz = (lane >> 4) << 3;
    const int br  = ((lane >> 4) << 3) + (lane & 7);
    const int bkz = ((lane >> 3) & 1) << 3;

#define COMP(s) do {                                                          \
        const uint32_t st = sb + (s) * STAGE_B;                               \
        const uint32_t Ah = st, Al = st + TILE_B;                             \
        const uint32_t Bh = st + 2 * TILE_B, Bl = st + 3 * TILE_B;            \
        _Pragma("unroll")                                                     \
        for (int kk = 0; kk < 2; ++kk) {                                      \
            uint32_t ahf[4][4], alf[4][4];                                    \
            _Pragma("unroll")                                                 \
            for (int i = 0; i < 4; ++i) {                                     \
                const uint32_t off =                                          \
                    (uint32_t)((wm * 64 + i * 16 + ar) * 80 + (kk * 16 + akz) * 2); \
                ldsm4(Ah + off, ahf[i][0], ahf[i][1], ahf[i][2], ahf[i][3]);  \
                ldsm4(Al + off, alf[i][0], alf[i][1], alf[i][2], alf[i][3]);  \
            }                                                                 \
            uint32_t bhf[2][4], blf[2][4];                                    \
            _Pragma("unroll")                                                 \
            for (int jj = 0; jj < 2; ++jj) {                                  \
                const uint32_t off =                                          \
                    (uint32_t)((wn * 32 + jj * 16 + br) * 80 + (kk * 16 + bkz) * 2); \
                ldsm4(Bh + off, bhf[jj][0], bhf[jj][1], bhf[jj][2], bhf[jj][3]); \
                ldsm4(Bl + off, blf[jj][0], blf[jj][1], blf[jj][2], blf[jj][3]); \
            }                                                                 \
            _Pragma("unroll")                                                 \
            for (int i = 0; i < 4; ++i)                                       \
                _Pragma("unroll")                                             \
                for (int j = 0; j < 4; ++j) {                                 \
                    const uint32_t b0h = bhf[j >> 1][(j & 1) * 2];            \
                    const uint32_t b1h = bhf[j >> 1][(j & 1) * 2 + 1];        \
                    const uint32_t b0l = blf[j >> 1][(j & 1) * 2];            \
                    const uint32_t b1l = blf[j >> 1][(j & 1) * 2 + 1];        \
                    mma16816(acc[i][j], ahf[i], b0h, b1h);                    \
                    mma16816(acc[i][j], ahf[i], b0l, b1l);                    \
                    mma16816(acc[i][j], alf[i], b0h, b1h);                    \
                }                                                             \
        }                                                                     \
    } while (0)

    LDGC(0);
    STSC(0);
    __syncthreads();

    for (int c = 0; c < 32; ++c) {
        if (c < 31) LDGC(c + 1);
        COMP(c & 1);
        if (c < 31) STSC((c + 1) & 1);
        __syncthreads();
    }
#undef LDGC
#undef STSC
#undef COMP

    const int g  = lane >> 2;
    const int qd = lane & 3;
#pragma unroll
    for (int i = 0; i < 4; ++i) {
        const int mA = m0 + wm * 64 + i * 16 + g;
        const int mB = mA + 8;
#pragma unroll
        for (int j = 0; j < 4; ++j) {
            const int n = n0 + wn * 32 + j * 8 + qd * 2;
            const float2 bv = *(const float2*)(bias + n);
            float2 o1, o2;
            o1.x = acc[i][j][0] + bv.x;  o1.y = acc[i][j][1] + bv.y;
            o2.x = acc[i][j][2] + bv.x;  o2.y = acc[i][j][3] + bv.y;
            if (HEAD) {
                const int h = n >> 6, dk = n & 63;
                const int b1 = mA >> 11, s1 = mA & 2047;
                const int b2 = mB >> 11, s2 = mB & 2047;
                const size_t i1 = ((size_t)((b1 * NH + h) * NS + s1)) * NDK + dk;
                const size_t i2 = ((size_t)((b2 * NH + h) * NS + s2)) * NDK + dk;
                uint32_t hh, ll;
                split2(o1, hh, ll);
                *(uint32_t*)(Oh + i1) = hh;  *(uint32_t*)(Ol + i1) = ll;
                split2(o2, hh, ll);
                *(uint32_t*)(Oh + i2) = hh;  *(uint32_t*)(Ol + i2) = ll;
            } else {
                *(float2*)(Out + (size_t)mA * ND + n) = o1;
                *(float2*)(Out + (size_t)mB * ND + n) = o2;
            }
        }
    }
}

__global__ __launch_bounds__(256)
void qkv_mma(const float* __restrict__ q,  const float* __restrict__ k,
             const float* __restrict__ v,
             const float* __restrict__ wq, const float* __restrict__ wk,
             const float* __restrict__ wv,
             const float* __restrict__ bq, const float* __restrict__ bk,
             const float* __restrict__ bv)
{
    const int z = blockIdx.z;
    const float* A  = (z == 0) ? q  : (z == 1) ? k  : v;
    const float* W  = (z == 0) ? wq : (z == 1) ? wk : wv;
    const float* bi = (z == 0) ? bq : (z == 1) ? bk : bv;
    __nv_bfloat16* Oh = (z == 0) ? g_Qh : (z == 1) ? g_Kh : g_Vh;
    __nv_bfloat16* Ol = (z == 0) ? g_Ql : (z == 1) ? g_Kl : g_Vl;
    gemm_mma_body<true>(A, W, bi, nullptr, Oh, Ol);
}

__global__ __launch_bounds__(256)
void oproj_mma(const float* __restrict__ wo, const float* __restrict__ bo,
               float* __restrict__ out)
{
    gemm_mma_body<false>(g_O, wo, bo, out, nullptr, nullptr);
}

// ===========================================================================
// Flash attention on mma.sync, split-bf16 3-term for QK^T and PV.
// CTA: 128 q-rows x (b,h); 8 warps x 16 rows; 32 key tiles of 64.
// Softmax base-2 (ex2.approx). K/V cp.async double-buffered.
// ===========================================================================
#define AQH   0u
#define AQL   18432u
#define ASTG0 36864u
#define ASTGSZ 36864u
#define AKH   0u
#define AKL   9216u
#define AVH   18432u
#define AVL   27648u
#define AMASK 110592u
#define ATTN_SMEM 118784
#define SCL  0.180336880f            /* 0.125 * log2(e) */
#define MV  -1.442695041e9f          /* -1e9 * log2(e)  */

__global__ __launch_bounds__(256)
void attn_mma(const int* __restrict__ mask)
{
    extern __shared__ char smem[];
    const uint32_t sb = smem_u32(smem);
    const int tid  = threadIdx.x;
    const int lane = tid & 31;
    const int w    = tid >> 5;
    const int qt   = blockIdx.x;
    const int h    = blockIdx.y;
    const int b    = blockIdx.z;
    const size_t kvb = (size_t)(b * NH + h) * NS * NDK;

    const int ar  = lane & 15;
    const int akz = (lane >> 4) << 3;
    const int br  = ((lane >> 4) << 3) + (lane & 7);
    const int bkz = ((lane >> 3) & 1) << 3;
    const int vr  = ((lane >> 3) & 1) * 8 + (lane & 7);
    const int vc  = (lane >> 4) << 3;
    const int g   = lane >> 2;
    const int q   = lane & 3;

    // Prologue: Q tile + mask + KV tile 0 (one cp.async group)
#pragma unroll
    for (int i = 0; i < 4; ++i) {
        const int li = tid + 256 * i, row = li >> 3, ch = li & 7;
        const size_t go = kvb + (size_t)(qt * 128 + row) * 64 + ch * 8;
        const uint32_t doff = (uint32_t)(row * 144 + ch * 16);
        cp16(sb + AQH + doff, g_Qh + go);
        cp16(sb + AQL + doff, g_Ql + go);
    }
#pragma unroll
    for (int i = 0; i < 2; ++i) {
        const int ck = tid + 256 * i;
        cp16(sb + AMASK + ck * 16, (const char*)(mask + b * NS) + ck * 16);
    }
#pragma unroll
    for (int i = 0; i < 2; ++i) {
        const int li = tid + 256 * i, row = li >> 3, ch = li & 7;
        const size_t go = kvb + (size_t)row * 64 + ch * 8;
        const uint32_t doff = (uint32_t)(row * 144 + ch * 16);
        cp16(sb + ASTG0 + AKH + doff, g_Kh + go);
        cp16(sb + ASTG0 + AKL + doff, g_Kl + go);
        cp16(sb + ASTG0 + AVH + doff, g_Vh + go);
        cp16(sb + ASTG0 + AVL + doff, g_Vl + go);
    }
    CP_COMMIT;

    float of[8][4];
#pragma unroll
    for (int j = 0; j < 8; ++j)
#pragma unroll
        for (int r = 0; r < 4; ++r) of[j][r] = 0.f;
    float m0 = -INFINITY, m1 = -INFINITY, l0 = 0.f, l1 = 0.f;
    uint32_t qh[4][4], ql[4][4];

    for (int t = 0; t < 32; ++t) {
        const uint32_t stg = sb + ASTG0 + (uint32_t)(t & 1) * ASTGSZ;
        if (t + 1 < 32) {
            const uint32_t nst = sb + ASTG0 + (uint32_t)((t + 1) & 1) * ASTGSZ;
#pragma unroll
            for (int i = 0; i < 2; ++i) {
                const int li = tid + 256 * i, row = li >> 3, ch = li & 7;
                const size_t go = kvb + (size_t)((t + 1) * 64 + row) * 64 + ch * 8;
                const uint32_t doff = (uint32_t)(row * 144 + ch * 16);
                cp16(nst + AKH + doff, g_Kh + go);
                cp16(nst + AKL + doff, g_Kl + go);
                cp16(nst + AVH + doff, g_Vh + go);
                cp16(nst + AVL + doff, g_Vl + go);
            }
            CP_COMMIT;
            CP_WAIT1;
        } else {
            CP_WAIT0;
        }
        __syncthreads();

        if (t == 0) {
#pragma unroll
            for (int kk = 0; kk < 4; ++kk) {
                const uint32_t off = (uint32_t)((w * 16 + ar) * 144 + (kk * 16 + akz) * 2);
                ldsm4(sb + AQH + off, qh[kk][0], qh[kk][1], qh[kk][2], qh[kk][3]);
                ldsm4(sb + AQL + off, ql[kk][0], ql[kk][1], ql[kk][2], ql[kk][3]);
            }
        }

        // ---- S = Q K^T (3-term split-bf16) ----
        float sf[8][4];
#pragma unroll
        for (int j = 0; j < 8; ++j)
#pragma unroll
            for (int r = 0; r < 4; ++r) sf[j][r] = 0.f;

#pragma unroll
        for (int kk = 0; kk < 4; ++kk) {
#pragma unroll
            for (int nh = 0; nh < 4; ++nh) {
                const uint32_t ka = stg + AKH +
                    (uint32_t)((nh * 16 + br) * 144 + (kk * 16 + bkz) * 2);
                uint32_t kh0, kh1, kh2, kh3, kl0, kl1, kl2, kl3;
                ldsm4(ka, kh0, kh1, kh2, kh3);
                ldsm4(ka + (AKL - AKH), kl0, kl1, kl2, kl3);
                mma16816(sf[2 * nh],     qh[kk], kh0, kh1);
                mma16816(sf[2 * nh],     qh[kk], kl0, kl1);
                mma16816(sf[2 * nh],     ql[kk], kh0, kh1);
                mma16816(sf[2 * nh + 1], qh[kk], kh2, kh3);
                mma16816(sf[2 * nh + 1], qh[kk], kl2, kl3);
                mma16816(sf[2 * nh + 1], ql[kk], kh2, kh3);
            }
        }

        // ---- scale + mask + online softmax (base 2) ----
#pragma unroll
        for (int j = 0; j < 8; ++j) {
            const int2 mk = *(const int2*)(smem + AMASK +
                                           (uint32_t)((t << 6) + (j << 3) + 2 * q) * 4);
            sf[j][0] = (mk.x == 0) ? MV : sf[j][0] * SCL;
            sf[j][1] = (mk.y == 0) ? MV : sf[j][1] * SCL;
            sf[j][2] = (mk.x == 0) ? MV : sf[j][2] * SCL;
            sf[j][3] = (mk.y == 0) ? MV : sf[j][3] * SCL;
        }
        float rm0 = sf[0][0], rm1 = sf[0][2];
#pragma unroll
        for (int j = 0; j < 8; ++j) {
            rm0 = fmaxf(rm0, fmaxf(sf[j][0], sf[j][1]));
            rm1 = fmaxf(rm1, fmaxf(sf[j][2], sf[j][3]));
        }
        rm0 = fmaxf(rm0, __shfl_xor_sync(0xffffffffu, rm0, 1));
        rm0 = fmaxf(rm0, __shfl_xor_sync(0xffffffffu, rm0, 2));
        rm1 = fmaxf(rm1, __shfl_xor_sync(0xffffffffu, rm1, 1));
        rm1 = fmaxf(rm1, __shfl_xor_sync(0xffffffffu, rm1, 2));

        const float m0n = fmaxf(m0, rm0);
        const float m1n = fmaxf(m1, rm1);
        const float a0 = ex2(m0 - m0n);
        const float a1 = ex2(m1 - m1n);
        m0 = m0n; m1 = m1n;

        float rs0 = 0.f, rs1 = 0.f;
#pragma unroll
        for (int j = 0; j < 8; ++j) {
            sf[j][0] = ex2(sf[j][0] - m0n);
            sf[j][1] = ex2(sf[j][1] - m0n);
            sf[j][2] = ex2(sf[j][2] - m1n);
            sf[j][3] = ex2(sf[j][3] - m1n);
            rs0 += sf[j][0] + sf[j][1];
            rs1 += sf[j][2] + sf[j][3];
        }
        rs0 += __shfl_xor_sync(0xffffffffu, rs0, 1);
        rs0 += __shfl_xor_sync(0xffffffffu, rs0, 2);
        rs1 += __shfl_xor_sync(0xffffffffu, rs1, 1);
        rs1 += __shfl_xor_sync(0xffffffffu, rs1, 2);
        l0 = l0 * a0 + rs0;
        l1 = l1 * a1 + rs1;
#pragma unroll
        for (int j = 0; j < 8; ++j) {
            of[j][0] *= a0; of[j][1] *= a0;
            of[j][2] *= a1; of[j][3] *= a1;
        }

        // ---- O += P V  (P split in-register; V via ldmatrix.trans) ----
#pragma unroll
        for (int kc = 0; kc < 4; ++kc) {
            uint32_t pah[4], pal[4];
            {
                const float* p0 = sf[2 * kc];
                const float* p1 = sf[2 * kc + 1];
                __nv_bfloat16 h00 = __float2bfloat16_rn(p0[0]);
                __nv_bfloat16 h01 = __float2bfloat16_rn(p0[1]);
                __nv_bfloat16 h02 = __float2bfloat16_rn(p0[2]);
                __nv_bfloat16 h03 = __float2bfloat16_rn(p0[3]);
                __nv_bfloat16 h10 = __float2bfloat16_rn(p1[0]);
                __nv_bfloat16 h11 = __float2bfloat16_rn(p1[1]);
                __nv_bfloat16 h12 = __float2bfloat16_rn(p1[2]);
                __nv_bfloat16 h13 = __float2bfloat16_rn(p1[3]);
                pah[0] = pack_bf2(h00, h01);
                pah[1] = pack_bf2(h02, h03);
                pah[2] = pack_bf2(h10, h11);
                pah[3] = pack_bf2(h12, h13);
                pal[0] = pack_bf2(__float2bfloat16_rn(p0[0] - __bfloat162float(h00)),
                                  __float2bfloat16_rn(p0[1] - __bfloat162float(h01)));
                pal[1] = pack_bf2(__float2bfloat16_rn(p0[2] - __bfloat162float(h02)),
                                  __float2bfloat16_rn(p0[3] - __bfloat162float(h03)));
                pal[2] = pack_bf2(__float2bfloat16_rn(p1[0] - __bfloat162float(h10)),
                                  __float2bfloat16_rn(p1[1] - __bfloat162float(h11)));
                pal[3] = pack_bf2(__float2bfloat16_rn(p1[2] - __bfloat162float(h12)),
                                  __float2bfloat16_rn(p1[3] - __bfloat162float(h13)));
            }
#pragma unroll
            for (int nh = 0; nh < 4; ++nh) {
                const uint32_t va = stg + AVH +
                    (uint32_t)((kc * 16 + vr) * 144 + (nh * 16 + vc) * 2);
                uint32_t vh0, vh1, vh2, vh3, vl0, vl1, vl2, vl3;
                ldsm4t(va, vh0, vh1, vh2, vh3);
                ldsm4t(va + (AVL - AVH), vl0, vl1, vl2, vl3);
                mma16816(of[2 * nh],     pah, vh0, vh1);
                mma16816(of[2 * nh],     pah, vl0, vl1);
                mma16816(of[2 * nh],     pal, vh0, vh1);
                mma16816(of[2 * nh + 1], pah, vh2, vh3);
                mma16816(of[2 * nh + 1], pah, vl2, vl3);
                mma16816(of[2 * nh + 1], pal, vh2, vh3);
            }
        }
        __syncthreads();
    }

    // Epilogue: normalize and write fp32 [b,s,d]
    const float i0 = 1.f / l0, i1 = 1.f / l1;
    const int r0 = qt * 128 + w * 16 + g;
    const int r1 = r0 + 8;
#pragma unroll
    for (int j = 0; j < 8; ++j) {
        const int col = h * 64 + j * 8 + 2 * q;
        float2 o0, o1;
        o0.x = of[j][0] * i0;  o0.y = of[j][1] * i0;
        o1.x = of[j][2] * i1;  o1.y = of[j][3] * i1;
        *(float2*)(g_O + (size_t)(b * NS + r0) * ND + col) = o0;
        *(float2*)(g_O + (size_t)(b * NS + r1) * ND + col) = o1;
    }
}

// ---------------------------------------------------------------------------
extern "C" void kernel_launch(void* const* d_in, const int* in_sizes, int n_in,
                              void* d_out, int out_size)
{
    (void)n_in; (void)out_size;
    const float *query, *key, *value, *wq, *bq, *wk, *bk, *wv, *bv, *wo, *bo;
    const int *mask;

    if (in_sizes[0] == NB * NS * ND) {
        query = (const float*)d_in[0];
        key   = (const float*)d_in[1];
        value = (const float*)d_in[2];
        mask  = (const int*)  d_in[3];
        wq    = (const float*)d_in[4];
        bq    = (const float*)d_in[5];
        wk    = (const float*)d_in[6];
        bk    = (const float*)d_in[7];
        wv    = (const float*)d_in[8];
        bv    = (const float*)d_in[9];
        wo    = (const float*)d_in[10];
        bo    = (const float*)d_in[11];
    } else {
        bk    = (const float*)d_in[0];
        bo    = (const float*)d_in[1];
        bq    = (const float*)d_in[2];
        bv    = (const float*)d_in[3];
        key   = (const float*)d_in[4];
        mask  = (const int*)  d_in[5];
        query = (const float*)d_in[6];
        value = (const float*)d_in[7];
        wk    = (const float*)d_in[8];
        wo    = (const float*)d_in[9];
        wq    = (const float*)d_in[10];
        wv    = (const float*)d_in[11];
    }

    cudaFuncSetAttribute(qkv_mma,   cudaFuncAttributeMaxDynamicSharedMemorySize, GEMM_SMEM);
    cudaFuncSetAttribute(oproj_mma, cudaFuncAttributeMaxDynamicSharedMemorySize, GEMM_SMEM);
    cudaFuncSetAttribute(attn_mma,  cudaFuncAttributeMaxDynamicSharedMemorySize, ATTN_SMEM);

    // 1) QKV projections -> bf16 hi/lo head-layout arrays
    qkv_mma<<<dim3(ND / 128, NBS / 128, 3), 256, GEMM_SMEM>>>(
        query, key, value, wq, wk, wv, bq, bk, bv);

    // 2) flash attention on tensor cores
    attn_mma<<<dim3(NS / 128, NH, NB), 256, ATTN_SMEM>>>(mask);

    // 3) output projection
    oproj_mma<<<dim3(ND / 128, NBS / 128, 1), 256, GEMM_SMEM>>>(wo, bo, (float*)d_out);
}

// round 7
// speedup vs baseline: 2.5714x; 1.0778x over previous
#include <cuda_runtime.h>
#include <cuda_bf16.h>
#include <math.h>
#include <stdint.h>

// Problem constants
#define NB 4
#define NS 2048
#define ND 1024
#define NH 16
#define NDK 64
#define NBS (NB*NS)   // 8192
#define INEL (NBS*ND) // 8388608

// Scratch (device globals — allocation-free per harness rules)
__device__ __nv_bfloat16 g_Qh[NB*NH*NS*NDK], g_Ql[NB*NH*NS*NDK];
__device__ __nv_bfloat16 g_Kh[NB*NH*NS*NDK], g_Kl[NB*NH*NS*NDK];
__device__ __nv_bfloat16 g_Vh[NB*NH*NS*NDK], g_Vl[NB*NH*NS*NDK];
__device__ __nv_bfloat16 g_Xh[3*INEL], g_Xl[3*INEL];       // split q,k,v
__device__ __nv_bfloat16 g_Wh[4*ND*ND], g_Wl[4*ND*ND];     // split wq,wk,wv,wo
__device__ __nv_bfloat16 g_AOh[INEL], g_AOl[INEL];         // split attn output

// ===========================================================================
// Helpers
// ===========================================================================
__device__ __forceinline__ uint32_t smem_u32(const void* p) {
    uint32_t a;
    asm("{ .reg .u64 t; cvta.to.shared.u64 t, %1; cvt.u32.u64 %0, t; }"
        : "=r"(a) : "l"(p));
    return a;
}
__device__ __forceinline__ void ldsm4(uint32_t addr, uint32_t& r0, uint32_t& r1,
                                      uint32_t& r2, uint32_t& r3) {
    asm volatile("ldmatrix.sync.aligned.m8n8.x4.shared.b16 {%0,%1,%2,%3}, [%4];"
                 : "=r"(r0), "=r"(r1), "=r"(r2), "=r"(r3) : "r"(addr));
}
__device__ __forceinline__ void ldsm4t(uint32_t addr, uint32_t& r0, uint32_t& r1,
                                       uint32_t& r2, uint32_t& r3) {
    asm volatile("ldmatrix.sync.aligned.m8n8.x4.trans.shared.b16 {%0,%1,%2,%3}, [%4];"
                 : "=r"(r0), "=r"(r1), "=r"(r2), "=r"(r3) : "r"(addr));
}
__device__ __forceinline__ void mma16816(float* c, const uint32_t* a,
                                         uint32_t b0, uint32_t b1) {
    asm volatile(
        "mma.sync.aligned.m16n8k16.row.col.f32.bf16.bf16.f32 "
        "{%0,%1,%2,%3}, {%4,%5,%6,%7}, {%8,%9}, {%0,%1,%2,%3};"
        : "+f"(c[0]), "+f"(c[1]), "+f"(c[2]), "+f"(c[3])
        : "r"(a[0]), "r"(a[1]), "r"(a[2]), "r"(a[3]), "r"(b0), "r"(b1));
}
__device__ __forceinline__ void cp16(uint32_t dst, const void* src) {
    asm volatile("cp.async.cg.shared.global [%0], [%1], 16;"
                 :: "r"(dst), "l"(src) : "memory");
}
#define CP_COMMIT asm volatile("cp.async.commit_group;" ::: "memory")
#define CP_WAIT2  asm volatile("cp.async.wait_group 2;" ::: "memory")
#define CP_WAIT1  asm volatile("cp.async.wait_group 1;" ::: "memory")
#define CP_WAIT0  asm volatile("cp.async.wait_group 0;" ::: "memory")

__device__ __forceinline__ float ex2(float x) {
    float y;
    asm("ex2.approx.f32 %0, %1;" : "=f"(y) : "f"(x));
    return y;
}
// packed bf16x2 convert: result low half = lo_val, high half = hi_val
__device__ __forceinline__ uint32_t cvt2(float hi_val, float lo_val) {
    uint32_t r;
    asm("cvt.rn.bf16x2.f32 %0, %1, %2;" : "=r"(r) : "f"(hi_val), "f"(lo_val));
    return r;
}
__device__ __forceinline__ float bflo(uint32_t u) { return __uint_as_float(u << 16); }
__device__ __forceinline__ float bfhi(uint32_t u) { return __uint_as_float(u & 0xffff0000u); }

__device__ __forceinline__ void split4c(float4 v, uint2& h, uint2& l) {
    h.x = cvt2(v.y, v.x);
    h.y = cvt2(v.w, v.z);
    l.x = cvt2(v.y - bfhi(h.x), v.x - bflo(h.x));
    l.y = cvt2(v.w - bfhi(h.y), v.z - bflo(h.y));
}
__device__ __forceinline__ void split2c(float2 v, uint32_t& h, uint32_t& l) {
    h = cvt2(v.y, v.x);
    l = cvt2(v.y - bfhi(h), v.x - bflo(h));
}

// ===========================================================================
// Pre-split pass: fp32 -> bf16 hi/lo arrays (DRAM-bound, ~50us total)
// ===========================================================================
__global__ __launch_bounds__(256)
void split_in(const float* __restrict__ q, const float* __restrict__ k,
              const float* __restrict__ v)
{
    const int z = blockIdx.y;
    const float* s = (z == 0) ? q : (z == 1) ? k : v;
    __nv_bfloat16* dh = g_Xh + (size_t)z * INEL;
    __nv_bfloat16* dl = g_Xl + (size_t)z * INEL;
    const size_t i4 = (size_t)blockIdx.x * 256 + threadIdx.x;   // float4 index
    float4 w = ((const float4*)s)[i4];
    uint2 h, l;
    split4c(w, h, l);
    ((uint2*)dh)[i4] = h;
    ((uint2*)dl)[i4] = l;
}

__global__ __launch_bounds__(256)
void split_w(const float* __restrict__ wq, const float* __restrict__ wk,
             const float* __restrict__ wv, const float* __restrict__ wo)
{
    const int z = blockIdx.y;
    const float* s = (z == 0) ? wq : (z == 1) ? wk : (z == 2) ? wv : wo;
    __nv_bfloat16* dh = g_Wh + (size_t)z * (ND * ND);
    __nv_bfloat16* dl = g_Wl + (size_t)z * (ND * ND);
    const size_t i4 = (size_t)blockIdx.x * 256 + threadIdx.x;
    float4 w = ((const float4*)s)[i4];
    uint2 h, l;
    split4c(w, h, l);
    ((uint2*)dh)[i4] = h;
    ((uint2*)dl)[i4] = l;
}

// ===========================================================================
// Pre-split TN GEMM (3-term): Out[m,n] = sum_k A[m,k]*W[n,k] + bias[n]
// All operands bf16 hi/lo in gmem. 128x128 tile, BK=32, cp.async 4-stage.
// ===========================================================================
#define PS_AH 0u
#define PS_AL 10240u
#define PS_BH 20480u
#define PS_BL 30720u
#define PS_STG 40960u
#define PS_SMEM (4*PS_STG)   // 163840 B

template <bool HEAD>
__device__ void gemm_ps(const __nv_bfloat16* __restrict__ Ah,
                        const __nv_bfloat16* __restrict__ Al,
                        const __nv_bfloat16* __restrict__ Bh,
                        const __nv_bfloat16* __restrict__ Bl,
                        const float* __restrict__ bias,
                        float* __restrict__ Out,
                        __nv_bfloat16* __restrict__ Oh,
                        __nv_bfloat16* __restrict__ Ol)
{
    extern __shared__ char smem[];
    const uint32_t sb = smem_u32(smem);
    const int tid  = threadIdx.x;
    const int lane = tid & 31;
    const int wid  = tid >> 5;
    const int wm   = wid >> 2;
    const int wn   = wid & 3;
    const int m0   = blockIdx.y * 128;
    const int n0   = blockIdx.x * 128;

    const __nv_bfloat16* Ahp = Ah + (size_t)m0 * ND;
    const __nv_bfloat16* Alp = Al + (size_t)m0 * ND;
    const __nv_bfloat16* Bhp = Bh + (size_t)n0 * ND;
    const __nv_bfloat16* Blp = Bl + (size_t)n0 * ND;

    float acc[4][4][4];
#pragma unroll
    for (int i = 0; i < 4; ++i)
#pragma unroll
        for (int j = 0; j < 4; ++j)
#pragma unroll
            for (int r = 0; r < 4; ++r) acc[i][j][r] = 0.f;

    // per-chunk loader: 4 tiles x 128 rows x 64B = 2048 x 16B; 8 cp16/thread
#define LOADC(c, slot) do {                                                   \
        const uint32_t dst = sb + (uint32_t)(slot) * PS_STG;                  \
        _Pragma("unroll")                                                     \
        for (int i = 0; i < 8; ++i) {                                         \
            const int li = tid + 256 * (i & 1);                               \
            const int r = li >> 2, cc = li & 3;                               \
            const uint32_t doff = (uint32_t)(r * 80 + cc * 16);               \
            const size_t so = (size_t)r * ND + (size_t)(c) * 32 + cc * 8;     \
            if (i < 2)      cp16(dst + PS_AH + doff, Ahp + so);               \
            else if (i < 4) cp16(dst + PS_AL + doff, Alp + so);               \
            else if (i < 6) cp16(dst + PS_BH + doff, Bhp + so);               \
            else            cp16(dst + PS_BL + doff, Blp + so);               \
        }                                                                     \
    } while (0)

    const int ar  = lane & 15;
    const int akz = (lane >> 4) << 3;
    const int br  = ((lane >> 4) << 3) + (lane & 7);
    const int bkz = ((lane >> 3) & 1) << 3;

#define COMPC(slot) do {                                                      \
        const uint32_t st = sb + (uint32_t)(slot) * PS_STG;                   \
        _Pragma("unroll")                                                     \
        for (int kk = 0; kk < 2; ++kk) {                                      \
            uint32_t ahf[4][4], alf[4][4];                                    \
            _Pragma("unroll")                                                 \
            for (int i = 0; i < 4; ++i) {                                     \
                const uint32_t off =                                          \
                    (uint32_t)((wm * 64 + i * 16 + ar) * 80 + (kk * 16 + akz) * 2); \
                ldsm4(st + PS_AH + off, ahf[i][0], ahf[i][1], ahf[i][2], ahf[i][3]); \
                ldsm4(st + PS_AL + off, alf[i][0], alf[i][1], alf[i][2], alf[i][3]); \
            }                                                                 \
            uint32_t bhf[2][4], blf[2][4];                                    \
            _Pragma("unroll")                                                 \
            for (int jj = 0; jj < 2; ++jj) {                                  \
                const uint32_t off =                                          \
                    (uint32_t)((wn * 32 + jj * 16 + br) * 80 + (kk * 16 + bkz) * 2); \
                ldsm4(st + PS_BH + off, bhf[jj][0], bhf[jj][1], bhf[jj][2], bhf[jj][3]); \
                ldsm4(st + PS_BL + off, blf[jj][0], blf[jj][1], blf[jj][2], blf[jj][3]); \
            }                                                                 \
            _Pragma("unroll")                                                 \
            for (int i = 0; i < 4; ++i)                                       \
                _Pragma("unroll")                                             \
                for (int j = 0; j < 4; ++j) {                                 \
                    const uint32_t b0h = bhf[j >> 1][(j & 1) * 2];            \
                    const uint32_t b1h = bhf[j >> 1][(j & 1) * 2 + 1];        \
                    const uint32_t b0l = blf[j >> 1][(j & 1) * 2];            \
                    const uint32_t b1l = blf[j >> 1][(j & 1) * 2 + 1];        \
                    mma16816(acc[i][j], ahf[i], b0h, b1h);                    \
                    mma16816(acc[i][j], ahf[i], b0l, b1l);                    \
                    mma16816(acc[i][j], alf[i], b0h, b1h);                    \
                }                                                             \
        }                                                                     \
    } while (0)

    LOADC(0, 0); CP_COMMIT;
    LOADC(1, 1); CP_COMMIT;
    LOADC(2, 2); CP_COMMIT;

    for (int c = 0; c < 32; ++c) {
        CP_WAIT2;                // chunk c resident
        __syncthreads();         // everyone done with slot (c+3)&3 from iter c-1
        if (c + 3 < 32) { LOADC(c + 3, (c + 3) & 3); }
        CP_COMMIT;               // uniform group accounting (may be empty)
        COMPC(c & 3);
    }
#undef LOADC
#undef COMPC

    // Epilogue
    const int g  = lane >> 2;
    const int qd = lane & 3;
#pragma unroll
    for (int i = 0; i < 4; ++i) {
        const int mA = m0 + wm * 64 + i * 16 + g;
        const int mB = mA + 8;
#pragma unroll
        for (int j = 0; j < 4; ++j) {
            const int n = n0 + wn * 32 + j * 8 + qd * 2;
            const float2 bv = *(const float2*)(bias + n);
            float2 o1, o2;
            o1.x = acc[i][j][0] + bv.x;  o1.y = acc[i][j][1] + bv.y;
            o2.x = acc[i][j][2] + bv.x;  o2.y = acc[i][j][3] + bv.y;
            if (HEAD) {
                const int h = n >> 6, dk = n & 63;
                const int b1 = mA >> 11, s1 = mA & 2047;
                const int b2 = mB >> 11, s2 = mB & 2047;
                const size_t i1 = ((size_t)((b1 * NH + h) * NS + s1)) * NDK + dk;
                const size_t i2 = ((size_t)((b2 * NH + h) * NS + s2)) * NDK + dk;
                uint32_t hh, ll;
                split2c(o1, hh, ll);
                *(uint32_t*)(Oh + i1) = hh;  *(uint32_t*)(Ol + i1) = ll;
                split2c(o2, hh, ll);
                *(uint32_t*)(Oh + i2) = hh;  *(uint32_t*)(Ol + i2) = ll;
            } else {
                *(float2*)(Out + (size_t)mA * ND + n) = o1;
                *(float2*)(Out + (size_t)mB * ND + n) = o2;
            }
        }
    }
}

__global__ __launch_bounds__(256)
void qkv_ps(const float* __restrict__ bq, const float* __restrict__ bk,
            const float* __restrict__ bv)
{
    const int z = blockIdx.z;
    const __nv_bfloat16* Ah = g_Xh + (size_t)z * INEL;
    const __nv_bfloat16* Al = g_Xl + (size_t)z * INEL;
    const __nv_bfloat16* Bh = g_Wh + (size_t)z * (ND * ND);
    const __nv_bfloat16* Bl = g_Wl + (size_t)z * (ND * ND);
    const float* bi = (z == 0) ? bq : (z == 1) ? bk : bv;
    __nv_bfloat16* Oh = (z == 0) ? g_Qh : (z == 1) ? g_Kh : g_Vh;
    __nv_bfloat16* Ol = (z == 0) ? g_Ql : (z == 1) ? g_Kl : g_Vl;
    gemm_ps<true>(Ah, Al, Bh, Bl, bi, nullptr, Oh, Ol);
}

__global__ __launch_bounds__(256)
void oproj_ps(const float* __restrict__ bo, float* __restrict__ out)
{
    gemm_ps<false>(g_AOh, g_AOl,
                   g_Wh + (size_t)3 * (ND * ND), g_Wl + (size_t)3 * (ND * ND),
                   bo, out, nullptr, nullptr);
}

// ===========================================================================
// Flash attention on mma.sync (round-6 proven core; epilogue now writes
// pre-split bf16 hi/lo for oproj; P-split uses packed cvt)
// ===========================================================================
#define AQH   0u
#define AQL   18432u
#define ASTG0 36864u
#define ASTGSZ 36864u
#define AKH   0u
#define AKL   9216u
#define AVH   18432u
#define AVL   27648u
#define AMASK 110592u
#define ATTN_SMEM 118784
#define SCL  0.180336880f            /* 0.125 * log2(e) */
#define MV  -1.442695041e9f          /* -1e9 * log2(e)  */

__global__ __launch_bounds__(256)
void attn_mma(const int* __restrict__ mask)
{
    extern __shared__ char smem[];
    const uint32_t sb = smem_u32(smem);
    const int tid  = threadIdx.x;
    const int lane = tid & 31;
    const int w    = tid >> 5;
    const int qt   = blockIdx.x;
    const int h    = blockIdx.y;
    const int b    = blockIdx.z;
    const size_t kvb = (size_t)(b * NH + h) * NS * NDK;

    const int ar  = lane & 15;
    const int akz = (lane >> 4) << 3;
    const int br  = ((lane >> 4) << 3) + (lane & 7);
    const int bkz = ((lane >> 3) & 1) << 3;
    const int vr  = ((lane >> 3) & 1) * 8 + (lane & 7);
    const int vc  = (lane >> 4) << 3;
    const int g   = lane >> 2;
    const int q   = lane & 3;

#pragma unroll
    for (int i = 0; i < 4; ++i) {
        const int li = tid + 256 * i, row = li >> 3, ch = li & 7;
        const size_t go = kvb + (size_t)(qt * 128 + row) * 64 + ch * 8;
        const uint32_t doff = (uint32_t)(row * 144 + ch * 16);
        cp16(sb + AQH + doff, g_Qh + go);
        cp16(sb + AQL + doff, g_Ql + go);
    }
#pragma unroll
    for (int i = 0; i < 2; ++i) {
        const int ck = tid + 256 * i;
        cp16(sb + AMASK + ck * 16, (const char*)(mask + b * NS) + ck * 16);
    }
#pragma unroll
    for (int i = 0; i < 2; ++i) {
        const int li = tid + 256 * i, row = li >> 3, ch = li & 7;
        const size_t go = kvb + (size_t)row * 64 + ch * 8;
        const uint32_t doff = (uint32_t)(row * 144 + ch * 16);
        cp16(sb + ASTG0 + AKH + doff, g_Kh + go);
        cp16(sb + ASTG0 + AKL + doff, g_Kl + go);
        cp16(sb + ASTG0 + AVH + doff, g_Vh + go);
        cp16(sb + ASTG0 + AVL + doff, g_Vl + go);
    }
    CP_COMMIT;

    float of[8][4];
#pragma unroll
    for (int j = 0; j < 8; ++j)
#pragma unroll
        for (int r = 0; r < 4; ++r) of[j][r] = 0.f;
    float m0 = -INFINITY, m1 = -INFINITY, l0 = 0.f, l1 = 0.f;
    uint32_t qh[4][4], ql[4][4];

    for (int t = 0; t < 32; ++t) {
        const uint32_t stg = sb + ASTG0 + (uint32_t)(t & 1) * ASTGSZ;
        if (t + 1 < 32) {
            const uint32_t nst = sb + ASTG0 + (uint32_t)((t + 1) & 1) * ASTGSZ;
#pragma unroll
            for (int i = 0; i < 2; ++i) {
                const int li = tid + 256 * i, row = li >> 3, ch = li & 7;
                const size_t go = kvb + (size_t)((t + 1) * 64 + row) * 64 + ch * 8;
                const uint32_t doff = (uint32_t)(row * 144 + ch * 16);
                cp16(nst + AKH + doff, g_Kh + go);
                cp16(nst + AKL + doff, g_Kl + go);
                cp16(nst + AVH + doff, g_Vh + go);
                cp16(nst + AVL + doff, g_Vl + go);
            }
            CP_COMMIT;
            CP_WAIT1;
        } else {
            CP_WAIT0;
        }
        __syncthreads();

        if (t == 0) {
#pragma unroll
            for (int kk = 0; kk < 4; ++kk) {
                const uint32_t off = (uint32_t)((w * 16 + ar) * 144 + (kk * 16 + akz) * 2);
                ldsm4(sb + AQH + off, qh[kk][0], qh[kk][1], qh[kk][2], qh[kk][3]);
                ldsm4(sb + AQL + off, ql[kk][0], ql[kk][1], ql[kk][2], ql[kk][3]);
            }
        }

        // ---- S = Q K^T (3-term split-bf16) ----
        float sf[8][4];
#pragma unroll
        for (int j = 0; j < 8; ++j)
#pragma unroll
            for (int r = 0; r < 4; ++r) sf[j][r] = 0.f;

#pragma unroll
        for (int kk = 0; kk < 4; ++kk) {
#pragma unroll
            for (int nh = 0; nh < 4; ++nh) {
                const uint32_t ka = stg + AKH +
                    (uint32_t)((nh * 16 + br) * 144 + (kk * 16 + bkz) * 2);
                uint32_t kh0, kh1, kh2, kh3, kl0, kl1, kl2, kl3;
                ldsm4(ka, kh0, kh1, kh2, kh3);
                ldsm4(ka + (AKL - AKH), kl0, kl1, kl2, kl3);
                mma16816(sf[2 * nh],     qh[kk], kh0, kh1);
                mma16816(sf[2 * nh],     qh[kk], kl0, kl1);
                mma16816(sf[2 * nh],     ql[kk], kh0, kh1);
                mma16816(sf[2 * nh + 1], qh[kk], kh2, kh3);
                mma16816(sf[2 * nh + 1], qh[kk], kl2, kl3);
                mma16816(sf[2 * nh + 1], ql[kk], kh2, kh3);
            }
        }

        // ---- scale + mask + online softmax (base 2) ----
#pragma unroll
        for (int j = 0; j < 8; ++j) {
            const int2 mk = *(const int2*)(smem + AMASK +
                                           (uint32_t)((t << 6) + (j << 3) + 2 * q) * 4);
            sf[j][0] = (mk.x == 0) ? MV : sf[j][0] * SCL;
            sf[j][1] = (mk.y == 0) ? MV : sf[j][1] * SCL;
            sf[j][2] = (mk.x == 0) ? MV : sf[j][2] * SCL;
            sf[j][3] = (mk.y == 0) ? MV : sf[j][3] * SCL;
        }
        float rm0 = sf[0][0], rm1 = sf[0][2];
#pragma unroll
        for (int j = 0; j < 8; ++j) {
            rm0 = fmaxf(rm0, fmaxf(sf[j][0], sf[j][1]));
            rm1 = fmaxf(rm1, fmaxf(sf[j][2], sf[j][3]));
        }
        rm0 = fmaxf(rm0, __shfl_xor_sync(0xffffffffu, rm0, 1));
        rm0 = fmaxf(rm0, __shfl_xor_sync(0xffffffffu, rm0, 2));
        rm1 = fmaxf(rm1, __shfl_xor_sync(0xffffffffu, rm1, 1));
        rm1 = fmaxf(rm1, __shfl_xor_sync(0xffffffffu, rm1, 2));

        const float m0n = fmaxf(m0, rm0);
        const float m1n = fmaxf(m1, rm1);
        const float a0 = ex2(m0 - m0n);
        const float a1 = ex2(m1 - m1n);
        m0 = m0n; m1 = m1n;

        float rs0 = 0.f, rs1 = 0.f;
#pragma unroll
        for (int j = 0; j < 8; ++j) {
            sf[j][0] = ex2(sf[j][0] - m0n);
            sf[j][1] = ex2(sf[j][1] - m0n);
            sf[j][2] = ex2(sf[j][2] - m1n);
            sf[j][3] = ex2(sf[j][3] - m1n);
            rs0 += sf[j][0] + sf[j][1];
            rs1 += sf[j][2] + sf[j][3];
        }
        rs0 += __shfl_xor_sync(0xffffffffu, rs0, 1);
        rs0 += __shfl_xor_sync(0xffffffffu, rs0, 2);
        rs1 += __shfl_xor_sync(0xffffffffu, rs1, 1);
        rs1 += __shfl_xor_sync(0xffffffffu, rs1, 2);
        l0 = l0 * a0 + rs0;
        l1 = l1 * a1 + rs1;
#pragma unroll
        for (int j = 0; j < 8; ++j) {
            of[j][0] *= a0; of[j][1] *= a0;
            of[j][2] *= a1; of[j][3] *= a1;
        }

        // ---- O += P V ----
#pragma unroll
        for (int kc = 0; kc < 4; ++kc) {
            uint32_t pah[4], pal[4];
            {
                const float* p0 = sf[2 * kc];
                const float* p1 = sf[2 * kc + 1];
                pah[0] = cvt2(p0[1], p0[0]);
                pah[1] = cvt2(p0[3], p0[2]);
                pah[2] = cvt2(p1[1], p1[0]);
                pah[3] = cvt2(p1[3], p1[2]);
                pal[0] = cvt2(p0[1] - bfhi(pah[0]), p0[0] - bflo(pah[0]));
                pal[1] = cvt2(p0[3] - bfhi(pah[1]), p0[2] - bflo(pah[1]));
                pal[2] = cvt2(p1[1] - bfhi(pah[2]), p1[0] - bflo(pah[2]));
                pal[3] = cvt2(p1[3] - bfhi(pah[3]), p1[2] - bflo(pah[3]));
            }
#pragma unroll
            for (int nh = 0; nh < 4; ++nh) {
                const uint32_t va = stg + AVH +
                    (uint32_t)((kc * 16 + vr) * 144 + (nh * 16 + vc) * 2);
                uint32_t vh0, vh1, vh2, vh3, vl0, vl1, vl2, vl3;
                ldsm4t(va, vh0, vh1, vh2, vh3);
                ldsm4t(va + (AVL - AVH), vl0, vl1, vl2, vl3);
                mma16816(of[2 * nh],     pah, vh0, vh1);
                mma16816(of[2 * nh],     pah, vl0, vl1);
                mma16816(of[2 * nh],     pal, vh0, vh1);
                mma16816(of[2 * nh + 1], pah, vh2, vh3);
                mma16816(of[2 * nh + 1], pah, vl2, vl3);
                mma16816(of[2 * nh + 1], pal, vh2, vh3);
            }
        }
        __syncthreads();
    }

    // Epilogue: normalize, split to bf16 hi/lo (oproj input)
    const float i0 = 1.f / l0, i1 = 1.f / l1;
    const int r0 = qt * 128 + w * 16 + g;
    const int r1 = r0 + 8;
#pragma unroll
    for (int j = 0; j < 8; ++j) {
        const int col = h * 64 + j * 8 + 2 * q;
        float2 o0, o1;
        o0.x = of[j][0] * i0;  o0.y = of[j][1] * i0;
        o1.x = of[j][2] * i1;  o1.y = of[j][3] * i1;
        uint32_t hh, ll;
        const size_t i0x = (size_t)(b * NS + r0) * ND + col;
        const size_t i1x = (size_t)(b * NS + r1) * ND + col;
        split2c(o0, hh, ll);
        *(uint32_t*)(g_AOh + i0x) = hh;  *(uint32_t*)(g_AOl + i0x) = ll;
        split2c(o1, hh, ll);
        *(uint32_t*)(g_AOh + i1x) = hh;  *(uint32_t*)(g_AOl + i1x) = ll;
    }
}

// ---------------------------------------------------------------------------
extern "C" void kernel_launch(void* const* d_in, const int* in_sizes, int n_in,
                              void* d_out, int out_size)
{
    (void)n_in; (void)out_size;
    const float *query, *key, *value, *wq, *bq, *wk, *bk, *wv, *bv, *wo, *bo;
    const int *mask;

    if (in_sizes[0] == NB * NS * ND) {
        query = (const float*)d_in[0];
        key   = (const float*)d_in[1];
        value = (const float*)d_in[2];
        mask  = (const int*)  d_in[3];
        wq    = (const float*)d_in[4];
        bq    = (const float*)d_in[5];
        wk    = (const float*)d_in[6];
        bk    = (const float*)d_in[7];
        wv    = (const float*)d_in[8];
        bv    = (const float*)d_in[9];
        wo    = (const float*)d_in[10];
        bo    = (const float*)d_in[11];
    } else {
        bk    = (const float*)d_in[0];
        bo    = (const float*)d_in[1];
        bq    = (const float*)d_in[2];
        bv    = (const float*)d_in[3];
        key   = (const float*)d_in[4];
        mask  = (const int*)  d_in[5];
        query = (const float*)d_in[6];
        value = (const float*)d_in[7];
        wk    = (const float*)d_in[8];
        wo    = (const float*)d_in[9];
        wq    = (const float*)d_in[10];
        wv    = (const float*)d_in[11];
    }

    cudaFuncSetAttribute(qkv_ps,   cudaFuncAttributeMaxDynamicSharedMemorySize, PS_SMEM);
    cudaFuncSetAttribute(oproj_ps, cudaFuncAttributeMaxDynamicSharedMemorySize, PS_SMEM);
    cudaFuncSetAttribute(attn_mma, cudaFuncAttributeMaxDynamicSharedMemorySize, ATTN_SMEM);

    // 0) pre-split inputs + weights to bf16 hi/lo
    split_in<<<dim3(INEL / 4 / 256, 3, 1), 256>>>(query, key, value);
    split_w<<<dim3(ND * ND / 4 / 256, 4, 1), 256>>>(wq, wk, wv, wo);

    // 1) QKV projections (pre-split, cp.async pipelined)
    qkv_ps<<<dim3(ND / 128, NBS / 128, 3), 256, PS_SMEM>>>(bq, bk, bv);

    // 2) flash attention on tensor cores
    attn_mma<<<dim3(NS / 128, NH, NB), 256, ATTN_SMEM>>>(mask);

    // 3) output projection
    oproj_ps<<<dim3(ND / 128, NBS / 128, 1), 256, PS_SMEM>>>(bo, (float*)d_out);
}

// round 8
// speedup vs baseline: 2.6243x; 1.0206x over previous
#include <cuda_runtime.h>
#include <cuda_bf16.h>
#include <math.h>
#include <stdint.h>

// Problem constants
#define NB 4
#define NS 2048
#define ND 1024
#define NH 16
#define NDK 64
#define NBS (NB*NS)   // 8192
#define INEL (NBS*ND) // 8388608

// Scratch (device globals — allocation-free per harness rules)
__device__ __nv_bfloat16 g_Qh[NB*NH*NS*NDK], g_Ql[NB*NH*NS*NDK];
__device__ __nv_bfloat16 g_Kh[NB*NH*NS*NDK], g_Kl[NB*NH*NS*NDK];
__device__ __nv_bfloat16 g_Vh[NB*NH*NS*NDK], g_Vl[NB*NH*NS*NDK];
__device__ __nv_bfloat16 g_Xh[3*INEL], g_Xl[3*INEL];       // split q,k,v
__device__ __nv_bfloat16 g_Wh[4*ND*ND], g_Wl[4*ND*ND];     // split wq,wk,wv,wo
__device__ __nv_bfloat16 g_AOh[INEL], g_AOl[INEL];         // split attn output

// ===========================================================================
// Helpers
// ===========================================================================
__device__ __forceinline__ uint32_t smem_u32(const void* p) {
    uint32_t a;
    asm("{ .reg .u64 t; cvta.to.shared.u64 t, %1; cvt.u32.u64 %0, t; }"
        : "=r"(a) : "l"(p));
    return a;
}
__device__ __forceinline__ void ldsm4(uint32_t addr, uint32_t& r0, uint32_t& r1,
                                      uint32_t& r2, uint32_t& r3) {
    asm volatile("ldmatrix.sync.aligned.m8n8.x4.shared.b16 {%0,%1,%2,%3}, [%4];"
                 : "=r"(r0), "=r"(r1), "=r"(r2), "=r"(r3) : "r"(addr));
}
__device__ __forceinline__ void ldsm4t(uint32_t addr, uint32_t& r0, uint32_t& r1,
                                       uint32_t& r2, uint32_t& r3) {
    asm volatile("ldmatrix.sync.aligned.m8n8.x4.trans.shared.b16 {%0,%1,%2,%3}, [%4];"
                 : "=r"(r0), "=r"(r1), "=r"(r2), "=r"(r3) : "r"(addr));
}
__device__ __forceinline__ void mma16816(float* c, const uint32_t* a,
                                         uint32_t b0, uint32_t b1) {
    asm volatile(
        "mma.sync.aligned.m16n8k16.row.col.f32.bf16.bf16.f32 "
        "{%0,%1,%2,%3}, {%4,%5,%6,%7}, {%8,%9}, {%0,%1,%2,%3};"
        : "+f"(c[0]), "+f"(c[1]), "+f"(c[2]), "+f"(c[3])
        : "r"(a[0]), "r"(a[1]), "r"(a[2]), "r"(a[3]), "r"(b0), "r"(b1));
}
__device__ __forceinline__ void cp16(uint32_t dst, const void* src) {
    asm volatile("cp.async.cg.shared.global [%0], [%1], 16;"
                 :: "r"(dst), "l"(src) : "memory");
}
#define CP_COMMIT asm volatile("cp.async.commit_group;" ::: "memory")
#define CP_WAIT2  asm volatile("cp.async.wait_group 2;" ::: "memory")
#define CP_WAIT1  asm volatile("cp.async.wait_group 1;" ::: "memory")
#define CP_WAIT0  asm volatile("cp.async.wait_group 0;" ::: "memory")

__device__ __forceinline__ float ex2(float x) {
    float y;
    asm("ex2.approx.f32 %0, %1;" : "=f"(y) : "f"(x));
    return y;
}
__device__ __forceinline__ uint32_t cvt2(float hi_val, float lo_val) {
    uint32_t r;
    asm("cvt.rn.bf16x2.f32 %0, %1, %2;" : "=r"(r) : "f"(hi_val), "f"(lo_val));
    return r;
}
__device__ __forceinline__ float bflo(uint32_t u) { return __uint_as_float(u << 16); }
__device__ __forceinline__ float bfhi(uint32_t u) { return __uint_as_float(u & 0xffff0000u); }

__device__ __forceinline__ void split4c(float4 v, uint2& h, uint2& l) {
    h.x = cvt2(v.y, v.x);
    h.y = cvt2(v.w, v.z);
    l.x = cvt2(v.y - bfhi(h.x), v.x - bflo(h.x));
    l.y = cvt2(v.w - bfhi(h.y), v.z - bflo(h.y));
}
__device__ __forceinline__ void split2c(float2 v, uint32_t& h, uint32_t& l) {
    h = cvt2(v.y, v.x);
    l = cvt2(v.y - bfhi(h), v.x - bflo(h));
}

// ===========================================================================
// Pre-split pass: fp32 -> bf16 hi/lo arrays (DRAM-bound)
// ===========================================================================
__global__ __launch_bounds__(256)
void split_in(const float* __restrict__ q, const float* __restrict__ k,
              const float* __restrict__ v)
{
    const int z = blockIdx.y;
    const float* s = (z == 0) ? q : (z == 1) ? k : v;
    __nv_bfloat16* dh = g_Xh + (size_t)z * INEL;
    __nv_bfloat16* dl = g_Xl + (size_t)z * INEL;
    const size_t i4 = (size_t)blockIdx.x * 256 + threadIdx.x;
    float4 w = ((const float4*)s)[i4];
    uint2 h, l;
    split4c(w, h, l);
    ((uint2*)dh)[i4] = h;
    ((uint2*)dl)[i4] = l;
}

__global__ __launch_bounds__(256)
void split_w(const float* __restrict__ wq, const float* __restrict__ wk,
             const float* __restrict__ wv, const float* __restrict__ wo)
{
    const int z = blockIdx.y;
    const float* s = (z == 0) ? wq : (z == 1) ? wk : (z == 2) ? wv : wo;
    __nv_bfloat16* dh = g_Wh + (size_t)z * (ND * ND);
    __nv_bfloat16* dl = g_Wl + (size_t)z * (ND * ND);
    const size_t i4 = (size_t)blockIdx.x * 256 + threadIdx.x;
    float4 w = ((const float4*)s)[i4];
    uint2 h, l;
    split4c(w, h, l);
    ((uint2*)dh)[i4] = h;
    ((uint2*)dl)[i4] = l;
}

// ===========================================================================
// Pre-split TN GEMM (3-term), 512 threads, 16 warps 4x4, warp tile 32x32.
// 128x128 CTA tile, BK=32, cp.async 4-stage.
// ===========================================================================
#define PS_AH 0u
#define PS_AL 10240u
#define PS_BH 20480u
#define PS_BL 30720u
#define PS_STG 40960u
#define PS_SMEM (4*PS_STG)   // 163840 B

template <bool HEAD>
__device__ void gemm_ps(const __nv_bfloat16* __restrict__ Ah,
                        const __nv_bfloat16* __restrict__ Al,
                        const __nv_bfloat16* __restrict__ Bh,
                        const __nv_bfloat16* __restrict__ Bl,
                        const float* __restrict__ bias,
                        float* __restrict__ Out,
                        __nv_bfloat16* __restrict__ Oh,
                        __nv_bfloat16* __restrict__ Ol)
{
    extern __shared__ char smem[];
    const uint32_t sb = smem_u32(smem);
    const int tid  = threadIdx.x;
    const int lane = tid & 31;
    const int wid  = tid >> 5;
    const int wm   = wid >> 2;     // 0..3
    const int wn   = wid & 3;      // 0..3
    const int m0   = blockIdx.y * 128;
    const int n0   = blockIdx.x * 128;

    const __nv_bfloat16* Ahp = Ah + (size_t)m0 * ND;
    const __nv_bfloat16* Alp = Al + (size_t)m0 * ND;
    const __nv_bfloat16* Bhp = Bh + (size_t)n0 * ND;
    const __nv_bfloat16* Blp = Bl + (size_t)n0 * ND;

    float acc[2][4][4];
#pragma unroll
    for (int i = 0; i < 2; ++i)
#pragma unroll
        for (int j = 0; j < 4; ++j)
#pragma unroll
            for (int r = 0; r < 4; ++r) acc[i][j][r] = 0.f;

    // loader: 4 tiles x 128 rows x 64B (4x16B); 512 threads -> 4 cp16 each
    const int lrow = tid >> 2;          // 0..127
    const int lcc  = tid & 3;           // 0..3
#define LOADC(c, slot) do {                                                   \
        const uint32_t dst = sb + (uint32_t)(slot) * PS_STG;                  \
        const uint32_t doff = (uint32_t)(lrow * 80 + lcc * 16);               \
        const size_t so = (size_t)lrow * ND + (size_t)(c) * 32 + lcc * 8;     \
        cp16(dst + PS_AH + doff, Ahp + so);                                   \
        cp16(dst + PS_AL + doff, Alp + so);                                   \
        cp16(dst + PS_BH + doff, Bhp + so);                                   \
        cp16(dst + PS_BL + doff, Blp + so);                                   \
    } while (0)

    const int ar  = lane & 15;
    const int akz = (lane >> 4) << 3;
    const int br  = ((lane >> 4) << 3) + (lane & 7);
    const int bkz = ((lane >> 3) & 1) << 3;

#define COMPC(slot) do {                                                      \
        const uint32_t st = sb + (uint32_t)(slot) * PS_STG;                   \
        _Pragma("unroll")                                                     \
        for (int kk = 0; kk < 2; ++kk) {                                      \
            uint32_t ahf[2][4], alf[2][4];                                    \
            _Pragma("unroll")                                                 \
            for (int i = 0; i < 2; ++i) {                                     \
                const uint32_t off =                                          \
                    (uint32_t)((wm * 32 + i * 16 + ar) * 80 + (kk * 16 + akz) * 2); \
                ldsm4(st + PS_AH + off, ahf[i][0], ahf[i][1], ahf[i][2], ahf[i][3]); \
                ldsm4(st + PS_AL + off, alf[i][0], alf[i][1], alf[i][2], alf[i][3]); \
            }                                                                 \
            uint32_t bhf[2][4], blf[2][4];                                    \
            _Pragma("unroll")                                                 \
            for (int jj = 0; jj < 2; ++jj) {                                  \
                const uint32_t off =                                          \
                    (uint32_t)((wn * 32 + jj * 16 + br) * 80 + (kk * 16 + bkz) * 2); \
                ldsm4(st + PS_BH + off, bhf[jj][0], bhf[jj][1], bhf[jj][2], bhf[jj][3]); \
                ldsm4(st + PS_BL + off, blf[jj][0], blf[jj][1], blf[jj][2], blf[jj][3]); \
            }                                                                 \
            _Pragma("unroll")                                                 \
            for (int i = 0; i < 2; ++i)                                       \
                _Pragma("unroll")                                             \
                for (int j = 0; j < 4; ++j) {                                 \
                    const uint32_t b0h = bhf[j >> 1][(j & 1) * 2];            \
                    const uint32_t b1h = bhf[j >> 1][(j & 1) * 2 + 1];        \
                    const uint32_t b0l = blf[j >> 1][(j & 1) * 2];            \
                    const uint32_t b1l = blf[j >> 1][(j & 1) * 2 + 1];        \
                    mma16816(acc[i][j], ahf[i], b0h, b1h);                    \
                    mma16816(acc[i][j], ahf[i], b0l, b1l);                    \
                    mma16816(acc[i][j], alf[i], b0h, b1h);                    \
                }                                                             \
        }                                                                     \
    } while (0)

    LOADC(0, 0); CP_COMMIT;
    LOADC(1, 1); CP_COMMIT;
    LOADC(2, 2); CP_COMMIT;

    for (int c = 0; c < 32; ++c) {
        CP_WAIT2;
        __syncthreads();
        if (c + 3 < 32) { LOADC(c + 3, (c + 3) & 3); }
        CP_COMMIT;
        COMPC(c & 3);
    }
#undef LOADC
#undef COMPC

    // Epilogue
    const int g  = lane >> 2;
    const int qd = lane & 3;
#pragma unroll
    for (int i = 0; i < 2; ++i) {
        const int mA = m0 + wm * 32 + i * 16 + g;
        const int mB = mA + 8;
#pragma unroll
        for (int j = 0; j < 4; ++j) {
            const int n = n0 + wn * 32 + j * 8 + qd * 2;
            const float2 bv = *(const float2*)(bias + n);
            float2 o1, o2;
            o1.x = acc[i][j][0] + bv.x;  o1.y = acc[i][j][1] + bv.y;
            o2.x = acc[i][j][2] + bv.x;  o2.y = acc[i][j][3] + bv.y;
            if (HEAD) {
                const int h = n >> 6, dk = n & 63;
                const int b1 = mA >> 11, s1 = mA & 2047;
                const int b2 = mB >> 11, s2 = mB & 2047;
                const size_t i1 = ((size_t)((b1 * NH + h) * NS + s1)) * NDK + dk;
                const size_t i2 = ((size_t)((b2 * NH + h) * NS + s2)) * NDK + dk;
                uint32_t hh, ll;
                split2c(o1, hh, ll);
                *(uint32_t*)(Oh + i1) = hh;  *(uint32_t*)(Ol + i1) = ll;
                split2c(o2, hh, ll);
                *(uint32_t*)(Oh + i2) = hh;  *(uint32_t*)(Ol + i2) = ll;
            } else {
                *(float2*)(Out + (size_t)mA * ND + n) = o1;
                *(float2*)(Out + (size_t)mB * ND + n) = o2;
            }
        }
    }
}

__global__ __launch_bounds__(512)
void qkv_ps(const float* __restrict__ bq, const float* __restrict__ bk,
            const float* __restrict__ bv)
{
    const int z = blockIdx.z;
    const __nv_bfloat16* Ah = g_Xh + (size_t)z * INEL;
    const __nv_bfloat16* Al = g_Xl + (size_t)z * INEL;
    const __nv_bfloat16* Bh = g_Wh + (size_t)z * (ND * ND);
    const __nv_bfloat16* Bl = g_Wl + (size_t)z * (ND * ND);
    const float* bi = (z == 0) ? bq : (z == 1) ? bk : bv;
    __nv_bfloat16* Oh = (z == 0) ? g_Qh : (z == 1) ? g_Kh : g_Vh;
    __nv_bfloat16* Ol = (z == 0) ? g_Ql : (z == 1) ? g_Kl : g_Vl;
    gemm_ps<true>(Ah, Al, Bh, Bl, bi, nullptr, Oh, Ol);
}

__global__ __launch_bounds__(512)
void oproj_ps(const float* __restrict__ bo, float* __restrict__ out)
{
    gemm_ps<false>(g_AOh, g_AOl,
                   g_Wh + (size_t)3 * (ND * ND), g_Wl + (size_t)3 * (ND * ND),
                   bo, out, nullptr, nullptr);
}

// ===========================================================================
// Flash attention, 512 threads / 16 warps, q-tile 256 (16 rows per warp),
// 64-key double-buffered KV stages, Q frags reloaded from smem per tile.
// ===========================================================================
#define AQH   0u
#define AQL   36864u
#define ASTG0 73728u
#define ASTGSZ 36864u
#define AKH   0u
#define AKL   9216u
#define AVH   18432u
#define AVL   27648u
#define AMASK 147456u
#define ATTN_SMEM 155648
#define SCL  0.180336880f            /* 0.125 * log2(e) */
#define MV  -1.442695041e9f          /* -1e9 * log2(e)  */

__global__ __launch_bounds__(512)
void attn_mma(const int* __restrict__ mask)
{
    extern __shared__ char smem[];
    const uint32_t sb = smem_u32(smem);
    const int tid  = threadIdx.x;
    const int lane = tid & 31;
    const int w    = tid >> 5;     // 0..15
    const int qt   = blockIdx.x;   // 0..7 (256 q-rows each)
    const int h    = blockIdx.y;
    const int b    = blockIdx.z;
    const size_t kvb = (size_t)(b * NH + h) * NS * NDK;

    const int ar  = lane & 15;
    const int akz = (lane >> 4) << 3;
    const int br  = ((lane >> 4) << 3) + (lane & 7);
    const int bkz = ((lane >> 3) & 1) << 3;
    const int vr  = ((lane >> 3) & 1) * 8 + (lane & 7);
    const int vc  = (lane >> 4) << 3;
    const int g   = lane >> 2;
    const int q   = lane & 3;

    // Prologue: Q (256 rows, hi+lo) + mask + KV tile 0 — one group
#pragma unroll
    for (int i = 0; i < 4; ++i) {
        const int li = tid + 512 * i;            // 0..2047
        const int row = li >> 3, ch = li & 7;    // row 0..255
        const size_t go = kvb + (size_t)(qt * 256 + row) * 64 + ch * 8;
        const uint32_t doff = (uint32_t)(row * 144 + ch * 16);
        cp16(sb + AQH + doff, g_Qh + go);
        cp16(sb + AQL + doff, g_Ql + go);
    }
    cp16(sb + AMASK + tid * 16, (const char*)(mask + b * NS) + tid * 16);
    {
        const int row = tid >> 3, ch = tid & 7;  // row 0..63
        const size_t go = kvb + (size_t)row * 64 + ch * 8;
        const uint32_t doff = (uint32_t)(row * 144 + ch * 16);
        cp16(sb + ASTG0 + AKH + doff, g_Kh + go);
        cp16(sb + ASTG0 + AKL + doff, g_Kl + go);
        cp16(sb + ASTG0 + AVH + doff, g_Vh + go);
        cp16(sb + ASTG0 + AVL + doff, g_Vl + go);
    }
    CP_COMMIT;

    float of[8][4];
#pragma unroll
    for (int j = 0; j < 8; ++j)
#pragma unroll
        for (int r = 0; r < 4; ++r) of[j][r] = 0.f;
    float m0 = -INFINITY, m1 = -INFINITY, l0 = 0.f, l1 = 0.f;

    for (int t = 0; t < 32; ++t) {
        const uint32_t stg = sb + ASTG0 + (uint32_t)(t & 1) * ASTGSZ;
        if (t + 1 < 32) {
            const uint32_t nst = sb + ASTG0 + (uint32_t)((t + 1) & 1) * ASTGSZ;
            const int row = tid >> 3, ch = tid & 7;
            const size_t go = kvb + (size_t)((t + 1) * 64 + row) * 64 + ch * 8;
            const uint32_t doff = (uint32_t)(row * 144 + ch * 16);
            cp16(nst + AKH + doff, g_Kh + go);
            cp16(nst + AKL + doff, g_Kl + go);
            cp16(nst + AVH + doff, g_Vh + go);
            cp16(nst + AVL + doff, g_Vl + go);
            CP_COMMIT;
            CP_WAIT1;
        } else {
            CP_WAIT0;
        }
        __syncthreads();

        // ---- S = Q K^T (3-term; Q frags reloaded per kk) ----
        float sf[8][4];
#pragma unroll
        for (int j = 0; j < 8; ++j)
#pragma unroll
            for (int r = 0; r < 4; ++r) sf[j][r] = 0.f;

#pragma unroll
        for (int kk = 0; kk < 4; ++kk) {
            uint32_t qh[4], ql[4];
            const uint32_t qoff = (uint32_t)((w * 16 + ar) * 144 + (kk * 16 + akz) * 2);
            ldsm4(sb + AQH + qoff, qh[0], qh[1], qh[2], qh[3]);
            ldsm4(sb + AQL + qoff, ql[0], ql[1], ql[2], ql[3]);
#pragma unroll
            for (int nh = 0; nh < 4; ++nh) {
                const uint32_t ka = stg + AKH +
                    (uint32_t)((nh * 16 + br) * 144 + (kk * 16 + bkz) * 2);
                uint32_t kh0, kh1, kh2, kh3, kl0, kl1, kl2, kl3;
                ldsm4(ka, kh0, kh1, kh2, kh3);
                ldsm4(ka + (AKL - AKH), kl0, kl1, kl2, kl3);
                mma16816(sf[2 * nh],     qh, kh0, kh1);
                mma16816(sf[2 * nh],     qh, kl0, kl1);
                mma16816(sf[2 * nh],     ql, kh0, kh1);
                mma16816(sf[2 * nh + 1], qh, kh2, kh3);
                mma16816(sf[2 * nh + 1], qh, kl2, kl3);
                mma16816(sf[2 * nh + 1], ql, kh2, kh3);
            }
        }

        // ---- scale + mask + online softmax (base 2) ----
#pragma unroll
        for (int j = 0; j < 8; ++j) {
            const int2 mk = *(const int2*)(smem + AMASK +
                                           (uint32_t)((t << 6) + (j << 3) + 2 * q) * 4);
            sf[j][0] = (mk.x == 0) ? MV : sf[j][0] * SCL;
            sf[j][1] = (mk.y == 0) ? MV : sf[j][1] * SCL;
            sf[j][2] = (mk.x == 0) ? MV : sf[j][2] * SCL;
            sf[j][3] = (mk.y == 0) ? MV : sf[j][3] * SCL;
        }
        float rm0 = sf[0][0], rm1 = sf[0][2];
#pragma unroll
        for (int j = 0; j < 8; ++j) {
            rm0 = fmaxf(rm0, fmaxf(sf[j][0], sf[j][1]));
            rm1 = fmaxf(rm1, fmaxf(sf[j][2], sf[j][3]));
        }
        rm0 = fmaxf(rm0, __shfl_xor_sync(0xffffffffu, rm0, 1));
        rm0 = fmaxf(rm0, __shfl_xor_sync(0xffffffffu, rm0, 2));
        rm1 = fmaxf(rm1, __shfl_xor_sync(0xffffffffu, rm1, 1));
        rm1 = fmaxf(rm1, __shfl_xor_sync(0xffffffffu, rm1, 2));

        const float m0n = fmaxf(m0, rm0);
        const float m1n = fmaxf(m1, rm1);
        const float a0 = ex2(m0 - m0n);
        const float a1 = ex2(m1 - m1n);
        m0 = m0n; m1 = m1n;

        float rs0 = 0.f, rs1 = 0.f;
#pragma unroll
        for (int j = 0; j < 8; ++j) {
            sf[j][0] = ex2(sf[j][0] - m0n);
            sf[j][1] = ex2(sf[j][1] - m0n);
            sf[j][2] = ex2(sf[j][2] - m1n);
            sf[j][3] = ex2(sf[j][3] - m1n);
            rs0 += sf[j][0] + sf[j][1];
            rs1 += sf[j][2] + sf[j][3];
        }
        rs0 += __shfl_xor_sync(0xffffffffu, rs0, 1);
        rs0 += __shfl_xor_sync(0xffffffffu, rs0, 2);
        rs1 += __shfl_xor_sync(0xffffffffu, rs1, 1);
        rs1 += __shfl_xor_sync(0xffffffffu, rs1, 2);
        l0 = l0 * a0 + rs0;
        l1 = l1 * a1 + rs1;
#pragma unroll
        for (int j = 0; j < 8; ++j) {
            of[j][0] *= a0; of[j][1] *= a0;
            of[j][2] *= a1; of[j][3] *= a1;
        }

        // ---- O += P V ----
#pragma unroll
        for (int kc = 0; kc < 4; ++kc) {
            uint32_t pah[4], pal[4];
            {
                const float* p0 = sf[2 * kc];
                const float* p1 = sf[2 * kc + 1];
                pah[0] = cvt2(p0[1], p0[0]);
                pah[1] = cvt2(p0[3], p0[2]);
                pah[2] = cvt2(p1[1], p1[0]);
                pah[3] = cvt2(p1[3], p1[2]);
                pal[0] = cvt2(p0[1] - bfhi(pah[0]), p0[0] - bflo(pah[0]));
                pal[1] = cvt2(p0[3] - bfhi(pah[1]), p0[2] - bflo(pah[1]));
                pal[2] = cvt2(p1[1] - bfhi(pah[2]), p1[0] - bflo(pah[2]));
                pal[3] = cvt2(p1[3] - bfhi(pah[3]), p1[2] - bflo(pah[3]));
            }
#pragma unroll
            for (int nh = 0; nh < 4; ++nh) {
                const uint32_t va = stg + AVH +
                    (uint32_t)((kc * 16 + vr) * 144 + (nh * 16 + vc) * 2);
                uint32_t vh0, vh1, vh2, vh3, vl0, vl1, vl2, vl3;
                ldsm4t(va, vh0, vh1, vh2, vh3);
                ldsm4t(va + (AVL - AVH), vl0, vl1, vl2, vl3);
                mma16816(of[2 * nh],     pah, vh0, vh1);
                mma16816(of[2 * nh],     pah, vl0, vl1);
                mma16816(of[2 * nh],     pal, vh0, vh1);
                mma16816(of[2 * nh + 1], pah, vh2, vh3);
                mma16816(of[2 * nh + 1], pah, vl2, vl3);
                mma16816(of[2 * nh + 1], pal, vh2, vh3);
            }
        }
        __syncthreads();
    }

    // Epilogue: normalize, split to bf16 hi/lo (oproj input)
    const float i0 = 1.f / l0, i1 = 1.f / l1;
    const int r0 = qt * 256 + w * 16 + g;
    const int r1 = r0 + 8;
#pragma unroll
    for (int j = 0; j < 8; ++j) {
        const int col = h * 64 + j * 8 + 2 * q;
        float2 o0, o1;
        o0.x = of[j][0] * i0;  o0.y = of[j][1] * i0;
        o1.x = of[j][2] * i1;  o1.y = of[j][3] * i1;
        uint32_t hh, ll;
        const size_t i0x = (size_t)(b * NS + r0) * ND + col;
        const size_t i1x = (size_t)(b * NS + r1) * ND + col;
        split2c(o0, hh, ll);
        *(uint32_t*)(g_AOh + i0x) = hh;  *(uint32_t*)(g_AOl + i0x) = ll;
        split2c(o1, hh, ll);
        *(uint32_t*)(g_AOh + i1x) = hh;  *(uint32_t*)(g_AOl + i1x) = ll;
    }
}

// ---------------------------------------------------------------------------
extern "C" void kernel_launch(void* const* d_in, const int* in_sizes, int n_in,
                              void* d_out, int out_size)
{
    (void)n_in; (void)out_size;
    const float *query, *key, *value, *wq, *bq, *wk, *bk, *wv, *bv, *wo, *bo;
    const int *mask;

    if (in_sizes[0] == NB * NS * ND) {
        query = (const float*)d_in[0];
        key   = (const float*)d_in[1];
        value = (const float*)d_in[2];
        mask  = (const int*)  d_in[3];
        wq    = (const float*)d_in[4];
        bq    = (const float*)d_in[5];
        wk    = (const float*)d_in[6];
        bk    = (const float*)d_in[7];
        wv    = (const float*)d_in[8];
        bv    = (const float*)d_in[9];
        wo    = (const float*)d_in[10];
        bo    = (const float*)d_in[11];
    } else {
        bk    = (const float*)d_in[0];
        bo    = (const float*)d_in[1];
        bq    = (const float*)d_in[2];
        bv    = (const float*)d_in[3];
        key   = (const float*)d_in[4];
        mask  = (const int*)  d_in[5];
        query = (const float*)d_in[6];
        value = (const float*)d_in[7];
        wk    = (const float*)d_in[8];
        wo    = (const float*)d_in[9];
        wq    = (const float*)d_in[10];
        wv    = (const float*)d_in[11];
    }

    cudaFuncSetAttribute(qkv_ps,   cudaFuncAttributeMaxDynamicSharedMemorySize, PS_SMEM);
    cudaFuncSetAttribute(oproj_ps, cudaFuncAttributeMaxDynamicSharedMemorySize, PS_SMEM);
    cudaFuncSetAttribute(attn_mma, cudaFuncAttributeMaxDynamicSharedMemorySize, ATTN_SMEM);

    // 0) pre-split inputs + weights to bf16 hi/lo
    split_in<<<dim3(INEL / 4 / 256, 3, 1), 256>>>(query, key, value);
    split_w<<<dim3(ND * ND / 4 / 256, 4, 1), 256>>>(wq, wk, wv, wo);

    // 1) QKV projections (512 threads, 16 warps)
    qkv_ps<<<dim3(ND / 128, NBS / 128, 3), 512, PS_SMEM>>>(bq, bk, bv);

    // 2) flash attention (512 threads, q-tile 256)
    attn_mma<<<dim3(NS / 256, NH, NB), 512, ATTN_SMEM>>>(mask);

    // 3) output projection
    oproj_ps<<<dim3(ND / 128, NBS / 128, 1), 512, PS_SMEM>>>(bo, (float*)d_out);
}